// round 2
// baseline (speedup 1.0000x reference)
#include <cuda_runtime.h>
#include <math.h>

// Problem constants
#define B_SZ   2
#define S_LEN  2048
#define D_DIM  2048
#define H_NUM  16
#define HD     128
#define M_ROWS (B_SZ * S_LEN)   // 4096

// ---------------------------------------------------------------------------
// Scratch (static device globals — allowed; runtime allocation is not)
// ---------------------------------------------------------------------------
__device__ float g_q  [M_ROWS * D_DIM];
__device__ float g_k  [M_ROWS * D_DIM];
__device__ float g_v  [M_ROWS * D_DIM];
__device__ float g_ctx[M_ROWS * D_DIM];

// ---------------------------------------------------------------------------
// SGEMM: C[M,N] = A[M,K] * B[N,K]^T   (both operands K-contiguous, row-major)
// 128x128 tile, BK=16, 256 threads, 8x8 per thread, double-buffered smem with
// register-staged global prefetch (single __syncthreads per k-slab).
// ---------------------------------------------------------------------------
#define GBM 128
#define GBN 128
#define GBK 16
#define GPAD 132   // smem row pitch in floats (16B aligned, conflict-reducing)

__global__ void __launch_bounds__(256)
sgemm_nt_kernel(const float* __restrict__ A, const float* __restrict__ B,
                float* __restrict__ C, int M, int N, int K)
{
    __shared__ float As[2][GBK][GPAD];
    __shared__ float Bs[2][GBK][GPAD];

    const int tid = threadIdx.x;
    const int bm = blockIdx.y * GBM;
    const int bn = blockIdx.x * GBN;
    const int tx = tid & 15;
    const int ty = tid >> 4;

    // Per-thread load tasks (2 for A, 2 for B): task f in 0..511
    // row = f>>2 (0..127), kk = (f&3)*4
    const int r0 = tid >> 2;          // task tid
    const int c0 = (tid & 3) * 4;
    const int r1 = (tid + 256) >> 2;  // task tid+256
    const int c1 = ((tid + 256) & 3) * 4;

    float acc[8][8];
#pragma unroll
    for (int i = 0; i < 8; i++)
#pragma unroll
        for (int j = 0; j < 8; j++) acc[i][j] = 0.f;

    // Preload slab 0 into buffer 0
    {
        float4 a0 = *(const float4*)&A[(size_t)(bm + r0) * K + c0];
        float4 a1 = *(const float4*)&A[(size_t)(bm + r1) * K + c1];
        float4 b0 = *(const float4*)&B[(size_t)(bn + r0) * K + c0];
        float4 b1 = *(const float4*)&B[(size_t)(bn + r1) * K + c1];
        As[0][c0 + 0][r0] = a0.x; As[0][c0 + 1][r0] = a0.y;
        As[0][c0 + 2][r0] = a0.z; As[0][c0 + 3][r0] = a0.w;
        As[0][c1 + 0][r1] = a1.x; As[0][c1 + 1][r1] = a1.y;
        As[0][c1 + 2][r1] = a1.z; As[0][c1 + 3][r1] = a1.w;
        Bs[0][c0 + 0][r0] = b0.x; Bs[0][c0 + 1][r0] = b0.y;
        Bs[0][c0 + 2][r0] = b0.z; Bs[0][c0 + 3][r0] = b0.w;
        Bs[0][c1 + 0][r1] = b1.x; Bs[0][c1 + 1][r1] = b1.y;
        Bs[0][c1 + 2][r1] = b1.z; Bs[0][c1 + 3][r1] = b1.w;
    }
    __syncthreads();

    int buf = 0;
    for (int k0 = 0; k0 < K; k0 += GBK) {
        const bool has_next = (k0 + GBK) < K;
        float4 pa0, pa1, pb0, pb1;
        if (has_next) {
            const int kn = k0 + GBK;
            pa0 = *(const float4*)&A[(size_t)(bm + r0) * K + kn + c0];
            pa1 = *(const float4*)&A[(size_t)(bm + r1) * K + kn + c1];
            pb0 = *(const float4*)&B[(size_t)(bn + r0) * K + kn + c0];
            pb1 = *(const float4*)&B[(size_t)(bn + r1) * K + kn + c1];
        }

#pragma unroll
        for (int k = 0; k < GBK; k++) {
            float af[8], bf[8];
            *(float4*)&af[0] = *(const float4*)&As[buf][k][ty * 4];
            *(float4*)&af[4] = *(const float4*)&As[buf][k][64 + ty * 4];
            *(float4*)&bf[0] = *(const float4*)&Bs[buf][k][tx * 4];
            *(float4*)&bf[4] = *(const float4*)&Bs[buf][k][64 + tx * 4];
#pragma unroll
            for (int i = 0; i < 8; i++)
#pragma unroll
                for (int j = 0; j < 8; j++)
                    acc[i][j] += af[i] * bf[j];
        }

        if (has_next) {
            const int nb = buf ^ 1;
            As[nb][c0 + 0][r0] = pa0.x; As[nb][c0 + 1][r0] = pa0.y;
            As[nb][c0 + 2][r0] = pa0.z; As[nb][c0 + 3][r0] = pa0.w;
            As[nb][c1 + 0][r1] = pa1.x; As[nb][c1 + 1][r1] = pa1.y;
            As[nb][c1 + 2][r1] = pa1.z; As[nb][c1 + 3][r1] = pa1.w;
            Bs[nb][c0 + 0][r0] = pb0.x; Bs[nb][c0 + 1][r0] = pb0.y;
            Bs[nb][c0 + 2][r0] = pb0.z; Bs[nb][c0 + 3][r0] = pb0.w;
            Bs[nb][c1 + 0][r1] = pb1.x; Bs[nb][c1 + 1][r1] = pb1.y;
            Bs[nb][c1 + 2][r1] = pb1.z; Bs[nb][c1 + 3][r1] = pb1.w;
            __syncthreads();
            buf = nb;
        }
    }

    // Epilogue: rows {ty*4+i, 64+ty*4+i}, cols {tx*4+j, 64+tx*4+j}
#pragma unroll
    for (int i = 0; i < 8; i++) {
        int r = bm + ((i < 4) ? (ty * 4 + i) : (64 + ty * 4 + (i - 4)));
        float4 o1 = make_float4(acc[i][0], acc[i][1], acc[i][2], acc[i][3]);
        float4 o2 = make_float4(acc[i][4], acc[i][5], acc[i][6], acc[i][7]);
        *(float4*)&C[(size_t)r * N + bn + tx * 4]      = o1;
        *(float4*)&C[(size_t)r * N + bn + 64 + tx * 4] = o2;
    }
}

// ---------------------------------------------------------------------------
// RoPE (interleaved pairs), in place on [M_ROWS, D_DIM].
// pair index p = h*64 + i ; angle = (m % S) * 10000^(-2i/128)
// ---------------------------------------------------------------------------
__global__ void rope_kernel(float* __restrict__ X)
{
    int idx = blockIdx.x * blockDim.x + threadIdx.x;     // one pair each
    if (idx >= M_ROWS * (D_DIM / 2)) return;
    int m = idx >> 10;            // / 1024 pairs per row
    int p = idx & 1023;
    int i = p & 63;               // pair index within head
    int s = m & (S_LEN - 1);      // position (m = b*S + s)

    float inv = powf(10000.f, -(float)(2 * i) / 128.f);
    float ang = (float)s * inv;
    float sv, cv;
    sincosf(ang, &sv, &cv);

    float2 x = *(float2*)&X[(size_t)idx * 2];
    float2 r;
    r.x = x.x * cv - x.y * sv;
    r.y = x.x * sv + x.y * cv;
    *(float2*)&X[(size_t)idx * 2] = r;
}

// ---------------------------------------------------------------------------
// Flash attention (causal), fp32. Per block: one 64-row q tile of one (b,h).
// Q,K staged d-major in smem (conflict-free LDS.128); V row-major; P staged
// through smem between the two GEMMs. Online softmax (m,l) per row.
// ---------------------------------------------------------------------------
#define FBM 64
#define FBN 64
#define QK_PITCH 68    // floats per d-row of Qt/Kt (16B aligned)
#define V_PITCH  132
#define P_PITCH  65

#define SM_QT   0
#define SM_KT   (128 * QK_PITCH)
#define SM_VS   (2 * 128 * QK_PITCH)
#define SM_PS   (2 * 128 * QK_PITCH + 64 * V_PITCH)
#define FLASH_SMEM_FLOATS (2 * 128 * QK_PITCH + 64 * V_PITCH + 64 * P_PITCH)

__global__ void __launch_bounds__(256, 1)
flash_kernel(const float* __restrict__ Qg, const float* __restrict__ Kg,
             const float* __restrict__ Vg, float* __restrict__ Og)
{
    extern __shared__ float sm[];
    float (*Qt)[QK_PITCH] = (float (*)[QK_PITCH])(sm + SM_QT);
    float (*Kt)[QK_PITCH] = (float (*)[QK_PITCH])(sm + SM_KT);
    float (*Vs)[V_PITCH]  = (float (*)[V_PITCH]) (sm + SM_VS);
    float (*Ps)[P_PITCH]  = (float (*)[P_PITCH]) (sm + SM_PS);

    const int tid = threadIdx.x;
    const int qt  = blockIdx.x;             // q tile: 0..31
    const int bh  = blockIdx.y;             // 0..31
    const int b   = bh >> 4;
    const int h   = bh & 15;
    const int q0  = qt * FBM;
    const size_t base = ((size_t)b * S_LEN) * D_DIM + (size_t)h * HD;

    // Load Q tile transposed: Qt[d][r], tasks = 128 d * 16 row-groups
#pragma unroll
    for (int it = 0; it < 8; it++) {
        int task = tid + it * 256;
        int d  = task & 127;
        int r4 = task >> 7;                  // 0..15
        const float* p = Qg + base + (size_t)(q0 + r4 * 4) * D_DIM + d;
        float4 val;
        val.x = p[0];
        val.y = p[D_DIM];
        val.z = p[2 * D_DIM];
        val.w = p[3 * D_DIM];
        *(float4*)&Qt[d][r4 * 4] = val;
    }

    const int tx = tid & 15;
    const int ty = tid >> 4;

    float acc[4][8];
    float mr[4], lr[4];
#pragma unroll
    for (int i = 0; i < 4; i++) {
        mr[i] = -1e30f; lr[i] = 0.f;
#pragma unroll
        for (int j = 0; j < 8; j++) acc[i][j] = 0.f;
    }

    const float scale = 0.08838834764831845f;   // 1/sqrt(128)
    const unsigned FULL = 0xffffffffu;

    for (int t = 0; t <= qt; t++) {
        const int k0 = t * FBN;
        __syncthreads();   // guard smem reuse from previous iteration / Qt fill

        // K transposed + V natural
#pragma unroll
        for (int it = 0; it < 8; it++) {
            int task = tid + it * 256;
            int d  = task & 127;
            int r4 = task >> 7;
            const float* p = Kg + base + (size_t)(k0 + r4 * 4) * D_DIM + d;
            float4 kv;
            kv.x = p[0];
            kv.y = p[D_DIM];
            kv.z = p[2 * D_DIM];
            kv.w = p[3 * D_DIM];
            *(float4*)&Kt[d][r4 * 4] = kv;

            int r  = task >> 5;
            int c4 = task & 31;
            *(float4*)&Vs[r][c4 * 4] =
                *(const float4*)(Vg + base + (size_t)(k0 + r) * D_DIM + c4 * 4);
        }
        __syncthreads();

        // S = Q K^T, rows ty*4+i, cols tx*4+j
        float s[4][4];
#pragma unroll
        for (int i = 0; i < 4; i++)
#pragma unroll
            for (int j = 0; j < 4; j++) s[i][j] = 0.f;

#pragma unroll 4
        for (int d = 0; d < HD; d++) {
            float qa[4], ka[4];
            *(float4*)qa = *(const float4*)&Qt[d][ty * 4];
            *(float4*)ka = *(const float4*)&Kt[d][tx * 4];
#pragma unroll
            for (int i = 0; i < 4; i++)
#pragma unroll
                for (int j = 0; j < 4; j++)
                    s[i][j] += qa[i] * ka[j];
        }

        // mask + online softmax per row
#pragma unroll
        for (int i = 0; i < 4; i++) {
            const int qrow = q0 + ty * 4 + i;
#pragma unroll
            for (int j = 0; j < 4; j++) {
                const int kcol = k0 + tx * 4 + j;
                float v = s[i][j] * scale;
                s[i][j] = (kcol <= qrow) ? v : -1e30f;
            }
            float mx = fmaxf(fmaxf(s[i][0], s[i][1]), fmaxf(s[i][2], s[i][3]));
#pragma unroll
            for (int off = 1; off < 16; off <<= 1)
                mx = fmaxf(mx, __shfl_xor_sync(FULL, mx, off));
            const float mnew = fmaxf(mr[i], mx);
            const float corr = __expf(mr[i] - mnew);
            mr[i] = mnew;
            float rs = 0.f;
#pragma unroll
            for (int j = 0; j < 4; j++) {
                float e = __expf(s[i][j] - mnew);
                s[i][j] = e;
                rs += e;
            }
#pragma unroll
            for (int off = 1; off < 16; off <<= 1)
                rs += __shfl_xor_sync(FULL, rs, off);
            lr[i] = lr[i] * corr + rs;
#pragma unroll
            for (int j = 0; j < 8; j++) acc[i][j] *= corr;
#pragma unroll
            for (int j = 0; j < 4; j++)
                Ps[ty * 4 + i][tx * 4 + j] = s[i][j];
        }
        __syncthreads();

        // acc += P * V ; cols {tx*4+j, 64+tx*4+j}
#pragma unroll 2
        for (int k = 0; k < FBN; k++) {
            float p0 = Ps[ty * 4 + 0][k];
            float p1 = Ps[ty * 4 + 1][k];
            float p2 = Ps[ty * 4 + 2][k];
            float p3 = Ps[ty * 4 + 3][k];
            float va[4], vb[4];
            *(float4*)va = *(const float4*)&Vs[k][tx * 4];
            *(float4*)vb = *(const float4*)&Vs[k][64 + tx * 4];
#pragma unroll
            for (int j = 0; j < 4; j++) {
                acc[0][j]     += p0 * va[j];
                acc[1][j]     += p1 * va[j];
                acc[2][j]     += p2 * va[j];
                acc[3][j]     += p3 * va[j];
                acc[0][j + 4] += p0 * vb[j];
                acc[1][j + 4] += p1 * vb[j];
                acc[2][j + 4] += p2 * vb[j];
                acc[3][j + 4] += p3 * vb[j];
            }
        }
    }

    // normalize + write ctx
#pragma unroll
    for (int i = 0; i < 4; i++) {
        const float inv = 1.f / lr[i];
        const int row = q0 + ty * 4 + i;
        float4 o1 = make_float4(acc[i][0] * inv, acc[i][1] * inv,
                                acc[i][2] * inv, acc[i][3] * inv);
        float4 o2 = make_float4(acc[i][4] * inv, acc[i][5] * inv,
                                acc[i][6] * inv, acc[i][7] * inv);
        *(float4*)(Og + base + (size_t)row * D_DIM + tx * 4)      = o1;
        *(float4*)(Og + base + (size_t)row * D_DIM + 64 + tx * 4) = o2;
    }
}

// ---------------------------------------------------------------------------
// Launcher
// ---------------------------------------------------------------------------
extern "C" void kernel_launch(void* const* d_in, const int* in_sizes, int n_in,
                              void* d_out, int out_size)
{
    const float* x  = (const float*)d_in[0];
    const float* Wq = (const float*)d_in[1];
    const float* Wk = (const float*)d_in[2];
    const float* Wv = (const float*)d_in[3];
    const float* Wo = (const float*)d_in[4];
    // d_in[5] = attn_mask: exactly causal; handled analytically in-kernel.
    float* out = (float*)d_out;

    float *q, *k, *v, *ctx;
    cudaGetSymbolAddress((void**)&q,   g_q);
    cudaGetSymbolAddress((void**)&k,   g_k);
    cudaGetSymbolAddress((void**)&v,   g_v);
    cudaGetSymbolAddress((void**)&ctx, g_ctx);

    const int smem_flash = FLASH_SMEM_FLOATS * (int)sizeof(float); // ~117 KB
    cudaFuncSetAttribute(flash_kernel,
                         cudaFuncAttributeMaxDynamicSharedMemorySize,
                         smem_flash);

    dim3 gemm_grid(D_DIM / GBN, M_ROWS / GBM);   // (16, 32)

    // Projections
    sgemm_nt_kernel<<<gemm_grid, 256>>>(x, Wq, q, M_ROWS, D_DIM, D_DIM);
    sgemm_nt_kernel<<<gemm_grid, 256>>>(x, Wk, k, M_ROWS, D_DIM, D_DIM);
    sgemm_nt_kernel<<<gemm_grid, 256>>>(x, Wv, v, M_ROWS, D_DIM, D_DIM);

    // RoPE on q and k
    const int rope_threads = M_ROWS * (D_DIM / 2);
    rope_kernel<<<(rope_threads + 255) / 256, 256>>>(q);
    rope_kernel<<<(rope_threads + 255) / 256, 256>>>(k);

    // Flash attention -> ctx
    dim3 flash_grid(S_LEN / FBM, B_SZ * H_NUM);  // (32, 32)
    flash_kernel<<<flash_grid, 256, smem_flash>>>(q, k, v, ctx);

    // Output projection
    sgemm_nt_kernel<<<gemm_grid, 256>>>(ctx, Wo, out, M_ROWS, D_DIM, D_DIM);
}

// round 4
// speedup vs baseline: 1.6358x; 1.6358x over previous
#include <cuda_runtime.h>
#include <cuda_bf16.h>
#include <math.h>
#include <cstdint>

// Problem constants
#define B_SZ   2
#define S_LEN  2048
#define D_DIM  2048
#define H_NUM  16
#define HD     128
#define M_ROWS (B_SZ * S_LEN)   // 4096

// ---------------------------------------------------------------------------
// Scratch (static device globals)
// ---------------------------------------------------------------------------
__device__ float g_q  [M_ROWS * D_DIM];
__device__ float g_k  [M_ROWS * D_DIM];
__device__ float g_v  [M_ROWS * D_DIM];
__device__ float g_ctx[M_ROWS * D_DIM];
__device__ __nv_bfloat16 g_ahi[M_ROWS * D_DIM];
__device__ __nv_bfloat16 g_alo[M_ROWS * D_DIM];
__device__ __nv_bfloat16 g_whi[D_DIM * D_DIM];
__device__ __nv_bfloat16 g_wlo[D_DIM * D_DIM];

// ---------------------------------------------------------------------------
// PTX helpers (sm_100 base ISA only: cp.async, ldmatrix, mma.sync)
// ---------------------------------------------------------------------------
__device__ __forceinline__ uint32_t smem_u32(const void* p) {
    uint32_t a;
    asm("{ .reg .u64 t; cvta.to.shared.u64 t, %1; cvt.u32.u64 %0, t; }"
        : "=r"(a) : "l"(p));
    return a;
}
__device__ __forceinline__ void cp16(uint32_t s, const void* g) {
    asm volatile("cp.async.cg.shared.global [%0], [%1], 16;" :: "r"(s), "l"(g));
}
#define CP_COMMIT() asm volatile("cp.async.commit_group;" ::: "memory")
#define CP_WAIT(n)  asm volatile("cp.async.wait_group %0;" :: "n"(n) : "memory")

__device__ __forceinline__ void ldsm_x4(uint32_t* r, uint32_t addr) {
    asm volatile("ldmatrix.sync.aligned.m8n8.x4.shared.b16 {%0,%1,%2,%3}, [%4];"
                 : "=r"(r[0]), "=r"(r[1]), "=r"(r[2]), "=r"(r[3]) : "r"(addr));
}
__device__ __forceinline__ void ldsm_x2(uint32_t* r, uint32_t addr) {
    asm volatile("ldmatrix.sync.aligned.m8n8.x2.shared.b16 {%0,%1}, [%2];"
                 : "=r"(r[0]), "=r"(r[1]) : "r"(addr));
}
__device__ __forceinline__ void mma16816(float* d, const uint32_t* a,
                                         const uint32_t* b) {
    asm volatile(
        "mma.sync.aligned.m16n8k16.row.col.f32.bf16.bf16.f32 "
        "{%0,%1,%2,%3}, {%4,%5,%6,%7}, {%8,%9}, {%0,%1,%2,%3};"
        : "+f"(d[0]), "+f"(d[1]), "+f"(d[2]), "+f"(d[3])
        : "r"(a[0]), "r"(a[1]), "r"(a[2]), "r"(a[3]), "r"(b[0]), "r"(b[1]));
}

// ---------------------------------------------------------------------------
// split: fp32 -> (hi bf16, lo bf16), lo = x - float(hi)
// ---------------------------------------------------------------------------
__global__ void split_kernel(const float* __restrict__ X,
                             __nv_bfloat16* __restrict__ H,
                             __nv_bfloat16* __restrict__ L, int n4)
{
    int i = blockIdx.x * blockDim.x + threadIdx.x;
    if (i >= n4) return;
    float4 v = ((const float4*)X)[i];
    __nv_bfloat16 h0 = __float2bfloat16(v.x);
    __nv_bfloat16 h1 = __float2bfloat16(v.y);
    __nv_bfloat16 h2 = __float2bfloat16(v.z);
    __nv_bfloat16 h3 = __float2bfloat16(v.w);
    __nv_bfloat16 l0 = __float2bfloat16(v.x - __bfloat162float(h0));
    __nv_bfloat16 l1 = __float2bfloat16(v.y - __bfloat162float(h1));
    __nv_bfloat16 l2 = __float2bfloat16(v.z - __bfloat162float(h2));
    __nv_bfloat16 l3 = __float2bfloat16(v.w - __bfloat162float(h3));
    ushort4 hh = make_ushort4(__bfloat16_as_ushort(h0), __bfloat16_as_ushort(h1),
                              __bfloat16_as_ushort(h2), __bfloat16_as_ushort(h3));
    ushort4 ll = make_ushort4(__bfloat16_as_ushort(l0), __bfloat16_as_ushort(l1),
                              __bfloat16_as_ushort(l2), __bfloat16_as_ushort(l3));
    ((ushort4*)H)[i] = hh;
    ((ushort4*)L)[i] = ll;
}

// ---------------------------------------------------------------------------
// HMMA bf16 split GEMM: C[M,N] = A[M,K] @ B[N,K]^T  (fp32 out, 3-pass hi/lo)
// CTA 128x128, BK=32, 256 threads (8 warps, 2x4), warp tile 64x32.
// smem pitch 40 bf16 (80 B) -> conflict-free ldmatrix.
// ---------------------------------------------------------------------------
#define BM 128
#define BN 128
#define BK 32
#define PIT 40                       // bf16 elems per smem row (80 B)
#define TILE_B (BM * PIT * 2)        // 10240 bytes per array
#define STAGE_B (4 * TILE_B)         // Ahi,Alo,Bhi,Blo = 40960
#define GEMM_SMEM (2 * STAGE_B)      // 81920

__device__ __forceinline__ void g_load_stage(
    uint32_t st, const __nv_bfloat16* __restrict__ Ah,
    const __nv_bfloat16* __restrict__ Al, const __nv_bfloat16* __restrict__ Bh,
    const __nv_bfloat16* __restrict__ Bl, int bm, int bn, int k0, int K, int tid)
{
    // 2048 chunks of 16B: 512 per array (128 rows x 4)
#pragma unroll
    for (int it = 0; it < 8; it++) {
        int c = tid + it * 256;
        int arr = c >> 9;
        int r   = (c & 511) >> 2;
        int c16 = c & 3;
        uint32_t dst = st + arr * TILE_B + r * (PIT * 2) + c16 * 16;
        const __nv_bfloat16* src;
        if (arr == 0)      src = Ah + (size_t)(bm + r) * K + k0 + c16 * 8;
        else if (arr == 1) src = Al + (size_t)(bm + r) * K + k0 + c16 * 8;
        else if (arr == 2) src = Bh + (size_t)(bn + r) * K + k0 + c16 * 8;
        else               src = Bl + (size_t)(bn + r) * K + k0 + c16 * 8;
        cp16(dst, src);
    }
}

__global__ void __launch_bounds__(256)
mma_gemm_kernel(const __nv_bfloat16* __restrict__ Ah,
                const __nv_bfloat16* __restrict__ Al,
                const __nv_bfloat16* __restrict__ Bh,
                const __nv_bfloat16* __restrict__ Bl,
                float* __restrict__ C, int M, int N, int K)
{
    extern __shared__ char smem[];
    const uint32_t sb = smem_u32(smem);

    const int tid  = threadIdx.x;
    const int wid  = tid >> 5;
    const int lane = tid & 31;
    const int wy   = wid >> 2;          // 0..1 (64-row bands)
    const int wx   = wid & 3;           // 0..3 (32-col bands)
    const int bm = blockIdx.y * BM;
    const int bn = blockIdx.x * BN;

    float acc[4][4][4];
#pragma unroll
    for (int mt = 0; mt < 4; mt++)
#pragma unroll
        for (int nt = 0; nt < 4; nt++)
#pragma unroll
            for (int e = 0; e < 4; e++) acc[mt][nt][e] = 0.f;

    // ldmatrix per-lane offsets
    const int a_row = wy * 64 + (lane & 15);
    const int a_kof = (lane >> 4) * 8;
    const int b_row = wx * 32 + (lane & 7);
    const int b_kof = ((lane >> 3) & 1) * 8;

    const int nk = K / BK;

    g_load_stage(sb, Ah, Al, Bh, Bl, bm, bn, 0, K, tid);
    CP_COMMIT();

    for (int i = 0; i < nk; i++) {
        const uint32_t st = sb + (i & 1) * STAGE_B;
        if (i + 1 < nk) {
            g_load_stage(sb + ((i + 1) & 1) * STAGE_B,
                         Ah, Al, Bh, Bl, bm, bn, (i + 1) * BK, K, tid);
            CP_COMMIT();
            CP_WAIT(1);
        } else {
            CP_WAIT(0);
        }
        __syncthreads();

        const uint32_t sAh = st;
        const uint32_t sAl = st + TILE_B;
        const uint32_t sBh = st + 2 * TILE_B;
        const uint32_t sBl = st + 3 * TILE_B;

#pragma unroll
        for (int ks = 0; ks < 2; ks++) {
            const int kk = ks * 16;
            uint32_t fah[4][4], fal[4][4], fbh[4][2], fbl[4][2];
#pragma unroll
            for (int mt = 0; mt < 4; mt++) {
                uint32_t off = (uint32_t)(a_row + mt * 16) * (PIT * 2)
                               + (uint32_t)(kk + a_kof) * 2;
                ldsm_x4(fah[mt], sAh + off);
                ldsm_x4(fal[mt], sAl + off);
            }
#pragma unroll
            for (int nt = 0; nt < 4; nt++) {
                uint32_t off = (uint32_t)(b_row + nt * 8) * (PIT * 2)
                               + (uint32_t)(kk + b_kof) * 2;
                ldsm_x2(fbh[nt], sBh + off);
                ldsm_x2(fbl[nt], sBl + off);
            }
#pragma unroll
            for (int mt = 0; mt < 4; mt++)
#pragma unroll
                for (int nt = 0; nt < 4; nt++) {
                    mma16816(acc[mt][nt], fah[mt], fbh[nt]);
                    mma16816(acc[mt][nt], fah[mt], fbl[nt]);
                    mma16816(acc[mt][nt], fal[mt], fbh[nt]);
                }
        }
        __syncthreads();
    }

    // Epilogue: direct fp32 stores
    const int er = lane >> 2;           // 0..7
    const int ec = (lane & 3) * 2;      // 0,2,4,6
#pragma unroll
    for (int mt = 0; mt < 4; mt++) {
        const int r0 = bm + wy * 64 + mt * 16 + er;
#pragma unroll
        for (int nt = 0; nt < 4; nt++) {
            const int c0 = bn + wx * 32 + nt * 8 + ec;
            *(float2*)&C[(size_t)r0 * N + c0] =
                make_float2(acc[mt][nt][0], acc[mt][nt][1]);
            *(float2*)&C[(size_t)(r0 + 8) * N + c0] =
                make_float2(acc[mt][nt][2], acc[mt][nt][3]);
        }
    }
}

// ---------------------------------------------------------------------------
// RoPE (interleaved pairs), in place on [M_ROWS, D_DIM].
// ---------------------------------------------------------------------------
__global__ void rope_kernel(float* __restrict__ X)
{
    int idx = blockIdx.x * blockDim.x + threadIdx.x;
    if (idx >= M_ROWS * (D_DIM / 2)) return;
    int m = idx >> 10;
    int p = idx & 1023;
    int i = p & 63;
    int s = m & (S_LEN - 1);

    float inv = powf(10000.f, -(float)(2 * i) / 128.f);
    float ang = (float)s * inv;
    float sv, cv;
    sincosf(ang, &sv, &cv);

    float2 x = *(float2*)&X[(size_t)idx * 2];
    float2 r;
    r.x = x.x * cv - x.y * sv;
    r.y = x.x * sv + x.y * cv;
    *(float2*)&X[(size_t)idx * 2] = r;
}

// ---------------------------------------------------------------------------
// Flash attention (causal), fp32 (unchanged from passing R2 version)
// ---------------------------------------------------------------------------
#define FBM 64
#define FBN 64
#define QK_PITCH 68
#define V_PITCH  132
#define P_PITCH  65

#define SM_QT   0
#define SM_KT   (128 * QK_PITCH)
#define SM_VS   (2 * 128 * QK_PITCH)
#define SM_PS   (2 * 128 * QK_PITCH + 64 * V_PITCH)
#define FLASH_SMEM_FLOATS (2 * 128 * QK_PITCH + 64 * V_PITCH + 64 * P_PITCH)

__global__ void __launch_bounds__(256, 1)
flash_kernel(const float* __restrict__ Qg, const float* __restrict__ Kg,
             const float* __restrict__ Vg, float* __restrict__ Og)
{
    extern __shared__ float sm[];
    float (*Qt)[QK_PITCH] = (float (*)[QK_PITCH])(sm + SM_QT);
    float (*Kt)[QK_PITCH] = (float (*)[QK_PITCH])(sm + SM_KT);
    float (*Vs)[V_PITCH]  = (float (*)[V_PITCH]) (sm + SM_VS);
    float (*Ps)[P_PITCH]  = (float (*)[P_PITCH]) (sm + SM_PS);

    const int tid = threadIdx.x;
    const int qt  = blockIdx.x;
    const int bh  = blockIdx.y;
    const int b   = bh >> 4;
    const int h   = bh & 15;
    const int q0  = qt * FBM;
    const size_t base = ((size_t)b * S_LEN) * D_DIM + (size_t)h * HD;

#pragma unroll
    for (int it = 0; it < 8; it++) {
        int task = tid + it * 256;
        int d  = task & 127;
        int r4 = task >> 7;
        const float* p = Qg + base + (size_t)(q0 + r4 * 4) * D_DIM + d;
        float4 val;
        val.x = p[0];
        val.y = p[D_DIM];
        val.z = p[2 * D_DIM];
        val.w = p[3 * D_DIM];
        *(float4*)&Qt[d][r4 * 4] = val;
    }

    const int tx = tid & 15;
    const int ty = tid >> 4;

    float acc[4][8];
    float mr[4], lr[4];
#pragma unroll
    for (int i = 0; i < 4; i++) {
        mr[i] = -1e30f; lr[i] = 0.f;
#pragma unroll
        for (int j = 0; j < 8; j++) acc[i][j] = 0.f;
    }

    const float scale = 0.08838834764831845f;
    const unsigned FULL = 0xffffffffu;

    for (int t = 0; t <= qt; t++) {
        const int k0 = t * FBN;
        __syncthreads();

#pragma unroll
        for (int it = 0; it < 8; it++) {
            int task = tid + it * 256;
            int d  = task & 127;
            int r4 = task >> 7;
            const float* p = Kg + base + (size_t)(k0 + r4 * 4) * D_DIM + d;
            float4 kv;
            kv.x = p[0];
            kv.y = p[D_DIM];
            kv.z = p[2 * D_DIM];
            kv.w = p[3 * D_DIM];
            *(float4*)&Kt[d][r4 * 4] = kv;

            int r  = task >> 5;
            int c4 = task & 31;
            *(float4*)&Vs[r][c4 * 4] =
                *(const float4*)(Vg + base + (size_t)(k0 + r) * D_DIM + c4 * 4);
        }
        __syncthreads();

        float s[4][4];
#pragma unroll
        for (int i = 0; i < 4; i++)
#pragma unroll
            for (int j = 0; j < 4; j++) s[i][j] = 0.f;

#pragma unroll 4
        for (int d = 0; d < HD; d++) {
            float qa[4], ka[4];
            *(float4*)qa = *(const float4*)&Qt[d][ty * 4];
            *(float4*)ka = *(const float4*)&Kt[d][tx * 4];
#pragma unroll
            for (int i = 0; i < 4; i++)
#pragma unroll
                for (int j = 0; j < 4; j++)
                    s[i][j] += qa[i] * ka[j];
        }

#pragma unroll
        for (int i = 0; i < 4; i++) {
            const int qrow = q0 + ty * 4 + i;
#pragma unroll
            for (int j = 0; j < 4; j++) {
                const int kcol = k0 + tx * 4 + j;
                float v = s[i][j] * scale;
                s[i][j] = (kcol <= qrow) ? v : -1e30f;
            }
            float mx = fmaxf(fmaxf(s[i][0], s[i][1]), fmaxf(s[i][2], s[i][3]));
#pragma unroll
            for (int off = 1; off < 16; off <<= 1)
                mx = fmaxf(mx, __shfl_xor_sync(FULL, mx, off));
            const float mnew = fmaxf(mr[i], mx);
            const float corr = __expf(mr[i] - mnew);
            mr[i] = mnew;
            float rs = 0.f;
#pragma unroll
            for (int j = 0; j < 4; j++) {
                float e = __expf(s[i][j] - mnew);
                s[i][j] = e;
                rs += e;
            }
#pragma unroll
            for (int off = 1; off < 16; off <<= 1)
                rs += __shfl_xor_sync(FULL, rs, off);
            lr[i] = lr[i] * corr + rs;
#pragma unroll
            for (int j = 0; j < 8; j++) acc[i][j] *= corr;
#pragma unroll
            for (int j = 0; j < 4; j++)
                Ps[ty * 4 + i][tx * 4 + j] = s[i][j];
        }
        __syncthreads();

#pragma unroll 2
        for (int k = 0; k < FBN; k++) {
            float p0 = Ps[ty * 4 + 0][k];
            float p1 = Ps[ty * 4 + 1][k];
            float p2 = Ps[ty * 4 + 2][k];
            float p3 = Ps[ty * 4 + 3][k];
            float va[4], vb[4];
            *(float4*)va = *(const float4*)&Vs[k][tx * 4];
            *(float4*)vb = *(const float4*)&Vs[k][64 + tx * 4];
#pragma unroll
            for (int j = 0; j < 4; j++) {
                acc[0][j]     += p0 * va[j];
                acc[1][j]     += p1 * va[j];
                acc[2][j]     += p2 * va[j];
                acc[3][j]     += p3 * va[j];
                acc[0][j + 4] += p0 * vb[j];
                acc[1][j + 4] += p1 * vb[j];
                acc[2][j + 4] += p2 * vb[j];
                acc[3][j + 4] += p3 * vb[j];
            }
        }
    }

#pragma unroll
    for (int i = 0; i < 4; i++) {
        const float inv = 1.f / lr[i];
        const int row = q0 + ty * 4 + i;
        float4 o1 = make_float4(acc[i][0] * inv, acc[i][1] * inv,
                                acc[i][2] * inv, acc[i][3] * inv);
        float4 o2 = make_float4(acc[i][4] * inv, acc[i][5] * inv,
                                acc[i][6] * inv, acc[i][7] * inv);
        *(float4*)(Og + base + (size_t)row * D_DIM + tx * 4)      = o1;
        *(float4*)(Og + base + (size_t)row * D_DIM + 64 + tx * 4) = o2;
    }
}

// ---------------------------------------------------------------------------
// Launcher
// ---------------------------------------------------------------------------
extern "C" void kernel_launch(void* const* d_in, const int* in_sizes, int n_in,
                              void* d_out, int out_size)
{
    const float* x  = (const float*)d_in[0];
    const float* Wq = (const float*)d_in[1];
    const float* Wk = (const float*)d_in[2];
    const float* Wv = (const float*)d_in[3];
    const float* Wo = (const float*)d_in[4];
    float* out = (float*)d_out;

    float *q, *k, *v, *ctx;
    __nv_bfloat16 *ahi, *alo, *whi, *wlo;
    cudaGetSymbolAddress((void**)&q,   g_q);
    cudaGetSymbolAddress((void**)&k,   g_k);
    cudaGetSymbolAddress((void**)&v,   g_v);
    cudaGetSymbolAddress((void**)&ctx, g_ctx);
    cudaGetSymbolAddress((void**)&ahi, g_ahi);
    cudaGetSymbolAddress((void**)&alo, g_alo);
    cudaGetSymbolAddress((void**)&whi, g_whi);
    cudaGetSymbolAddress((void**)&wlo, g_wlo);

    cudaFuncSetAttribute(mma_gemm_kernel,
                         cudaFuncAttributeMaxDynamicSharedMemorySize, GEMM_SMEM);
    const int smem_flash = FLASH_SMEM_FLOATS * (int)sizeof(float);
    cudaFuncSetAttribute(flash_kernel,
                         cudaFuncAttributeMaxDynamicSharedMemorySize, smem_flash);

    const int nx4 = (M_ROWS * D_DIM) / 4;
    const int nw4 = (D_DIM * D_DIM) / 4;
    dim3 ggrid(D_DIM / BN, M_ROWS / BM);    // (16, 32)

    // x -> bf16 hi/lo
    split_kernel<<<(nx4 + 255) / 256, 256>>>(x, ahi, alo, nx4);

    // Q/K/V projections
    split_kernel<<<(nw4 + 255) / 256, 256>>>(Wq, whi, wlo, nw4);
    mma_gemm_kernel<<<ggrid, 256, GEMM_SMEM>>>(ahi, alo, whi, wlo, q,
                                               M_ROWS, D_DIM, D_DIM);
    split_kernel<<<(nw4 + 255) / 256, 256>>>(Wk, whi, wlo, nw4);
    mma_gemm_kernel<<<ggrid, 256, GEMM_SMEM>>>(ahi, alo, whi, wlo, k,
                                               M_ROWS, D_DIM, D_DIM);
    split_kernel<<<(nw4 + 255) / 256, 256>>>(Wv, whi, wlo, nw4);
    mma_gemm_kernel<<<ggrid, 256, GEMM_SMEM>>>(ahi, alo, whi, wlo, v,
                                               M_ROWS, D_DIM, D_DIM);

    // RoPE
    const int rope_threads = M_ROWS * (D_DIM / 2);
    rope_kernel<<<(rope_threads + 255) / 256, 256>>>(q);
    rope_kernel<<<(rope_threads + 255) / 256, 256>>>(k);

    // Flash attention
    dim3 flash_grid(S_LEN / FBM, B_SZ * H_NUM);
    flash_kernel<<<flash_grid, 256, smem_flash>>>(q, k, v, ctx);

    // Output projection
    split_kernel<<<(nx4 + 255) / 256, 256>>>(ctx, ahi, alo, nx4);
    split_kernel<<<(nw4 + 255) / 256, 256>>>(Wo, whi, wlo, nw4);
    mma_gemm_kernel<<<ggrid, 256, GEMM_SMEM>>>(ahi, alo, whi, wlo, out,
                                               M_ROWS, D_DIM, D_DIM);
}

// round 5
// speedup vs baseline: 2.5633x; 1.5670x over previous
#include <cuda_runtime.h>
#include <cuda_bf16.h>
#include <math.h>
#include <cstdint>

// Problem constants
#define B_SZ   2
#define S_LEN  2048
#define D_DIM  2048
#define H_NUM  16
#define HD     128
#define M_ROWS (B_SZ * S_LEN)   // 4096

// ---------------------------------------------------------------------------
// Scratch (static device globals)
// ---------------------------------------------------------------------------
__device__ float g_q  [M_ROWS * D_DIM];
__device__ float g_k  [M_ROWS * D_DIM];
__device__ float g_v  [M_ROWS * D_DIM];
__device__ float g_ctx[M_ROWS * D_DIM];
__device__ __nv_bfloat16 g_ahi[M_ROWS * D_DIM];
__device__ __nv_bfloat16 g_alo[M_ROWS * D_DIM];
__device__ __nv_bfloat16 g_whi[D_DIM * D_DIM];
__device__ __nv_bfloat16 g_wlo[D_DIM * D_DIM];
__device__ __nv_bfloat16 g_qh [M_ROWS * D_DIM];
__device__ __nv_bfloat16 g_ql [M_ROWS * D_DIM];
__device__ __nv_bfloat16 g_kh [M_ROWS * D_DIM];
__device__ __nv_bfloat16 g_kl [M_ROWS * D_DIM];
__device__ __nv_bfloat16 g_vh [M_ROWS * D_DIM];
__device__ __nv_bfloat16 g_vl [M_ROWS * D_DIM];

// ---------------------------------------------------------------------------
// PTX helpers (sm_100 base ISA only: cp.async, ldmatrix, mma.sync)
// ---------------------------------------------------------------------------
__device__ __forceinline__ uint32_t smem_u32(const void* p) {
    uint32_t a;
    asm("{ .reg .u64 t; cvta.to.shared.u64 t, %1; cvt.u32.u64 %0, t; }"
        : "=r"(a) : "l"(p));
    return a;
}
__device__ __forceinline__ void cp16(uint32_t s, const void* g) {
    asm volatile("cp.async.cg.shared.global [%0], [%1], 16;" :: "r"(s), "l"(g));
}
#define CP_COMMIT() asm volatile("cp.async.commit_group;" ::: "memory")
#define CP_WAIT(n)  asm volatile("cp.async.wait_group %0;" :: "n"(n) : "memory")

__device__ __forceinline__ void ldsm_x4(uint32_t* r, uint32_t addr) {
    asm volatile("ldmatrix.sync.aligned.m8n8.x4.shared.b16 {%0,%1,%2,%3}, [%4];"
                 : "=r"(r[0]), "=r"(r[1]), "=r"(r[2]), "=r"(r[3]) : "r"(addr));
}
__device__ __forceinline__ void ldsm_x4_t(uint32_t* r, uint32_t addr) {
    asm volatile("ldmatrix.sync.aligned.m8n8.x4.trans.shared.b16 {%0,%1,%2,%3}, [%4];"
                 : "=r"(r[0]), "=r"(r[1]), "=r"(r[2]), "=r"(r[3]) : "r"(addr));
}
__device__ __forceinline__ void ldsm_x2(uint32_t* r, uint32_t addr) {
    asm volatile("ldmatrix.sync.aligned.m8n8.x2.shared.b16 {%0,%1}, [%2];"
                 : "=r"(r[0]), "=r"(r[1]) : "r"(addr));
}
__device__ __forceinline__ void mma16816(float* d, const uint32_t* a,
                                         const uint32_t* b) {
    asm volatile(
        "mma.sync.aligned.m16n8k16.row.col.f32.bf16.bf16.f32 "
        "{%0,%1,%2,%3}, {%4,%5,%6,%7}, {%8,%9}, {%0,%1,%2,%3};"
        : "+f"(d[0]), "+f"(d[1]), "+f"(d[2]), "+f"(d[3])
        : "r"(a[0]), "r"(a[1]), "r"(a[2]), "r"(a[3]), "r"(b[0]), "r"(b[1]));
}
__device__ __forceinline__ float ex2(float x) {
    float y;
    asm("ex2.approx.ftz.f32 %0, %1;" : "=f"(y) : "f"(x));
    return y;
}
__device__ __forceinline__ uint32_t pk_hi(float a, float b) {
    __nv_bfloat162 t = __floats2bfloat162_rn(a, b);
    return *(uint32_t*)&t;
}
__device__ __forceinline__ uint32_t pk_lo(float a, float b, uint32_t hi) {
    __nv_bfloat162 h = *(__nv_bfloat162*)&hi;
    return pk_hi(a - __bfloat162float(h.x), b - __bfloat162float(h.y));
}

// ---------------------------------------------------------------------------
// split: fp32 -> (hi bf16, lo bf16), lo = x - float(hi)
// ---------------------------------------------------------------------------
__global__ void split_kernel(const float* __restrict__ X,
                             __nv_bfloat16* __restrict__ H,
                             __nv_bfloat16* __restrict__ L, int n4)
{
    int i = blockIdx.x * blockDim.x + threadIdx.x;
    if (i >= n4) return;
    float4 v = ((const float4*)X)[i];
    __nv_bfloat16 h0 = __float2bfloat16(v.x);
    __nv_bfloat16 h1 = __float2bfloat16(v.y);
    __nv_bfloat16 h2 = __float2bfloat16(v.z);
    __nv_bfloat16 h3 = __float2bfloat16(v.w);
    __nv_bfloat16 l0 = __float2bfloat16(v.x - __bfloat162float(h0));
    __nv_bfloat16 l1 = __float2bfloat16(v.y - __bfloat162float(h1));
    __nv_bfloat16 l2 = __float2bfloat16(v.z - __bfloat162float(h2));
    __nv_bfloat16 l3 = __float2bfloat16(v.w - __bfloat162float(h3));
    ushort4 hh = make_ushort4(__bfloat16_as_ushort(h0), __bfloat16_as_ushort(h1),
                              __bfloat16_as_ushort(h2), __bfloat16_as_ushort(h3));
    ushort4 ll = make_ushort4(__bfloat16_as_ushort(l0), __bfloat16_as_ushort(l1),
                              __bfloat16_as_ushort(l2), __bfloat16_as_ushort(l3));
    ((ushort4*)H)[i] = hh;
    ((ushort4*)L)[i] = ll;
}

// ---------------------------------------------------------------------------
// rope_split: fp32 rope-rotated pair -> bf16 hi/lo
// ---------------------------------------------------------------------------
__global__ void rope_split_kernel(const float* __restrict__ X,
                                  __nv_bfloat16* __restrict__ H,
                                  __nv_bfloat16* __restrict__ L)
{
    int idx = blockIdx.x * blockDim.x + threadIdx.x;
    if (idx >= M_ROWS * (D_DIM / 2)) return;
    int m = idx >> 10;
    int p = idx & 1023;
    int i = p & 63;
    int s = m & (S_LEN - 1);

    float inv = powf(10000.f, -(float)(2 * i) / 128.f);
    float ang = (float)s * inv;
    float sv, cv;
    sincosf(ang, &sv, &cv);

    float2 x = *(const float2*)&X[(size_t)idx * 2];
    float rx = x.x * cv - x.y * sv;
    float ry = x.x * sv + x.y * cv;
    uint32_t h = pk_hi(rx, ry);
    uint32_t l = pk_lo(rx, ry, h);
    ((uint32_t*)H)[idx] = h;
    ((uint32_t*)L)[idx] = l;
}

// ---------------------------------------------------------------------------
// HMMA bf16 split GEMM (unchanged from R4): C = A @ B^T, 3-pass hi/lo
// ---------------------------------------------------------------------------
#define BM 128
#define BN 128
#define BK 32
#define PIT 40
#define TILE_B (BM * PIT * 2)
#define STAGE_B (4 * TILE_B)
#define GEMM_SMEM (2 * STAGE_B)

__device__ __forceinline__ void g_load_stage(
    uint32_t st, const __nv_bfloat16* __restrict__ Ah,
    const __nv_bfloat16* __restrict__ Al, const __nv_bfloat16* __restrict__ Bh,
    const __nv_bfloat16* __restrict__ Bl, int bm, int bn, int k0, int K, int tid)
{
#pragma unroll
    for (int it = 0; it < 8; it++) {
        int c = tid + it * 256;
        int arr = c >> 9;
        int r   = (c & 511) >> 2;
        int c16 = c & 3;
        uint32_t dst = st + arr * TILE_B + r * (PIT * 2) + c16 * 16;
        const __nv_bfloat16* src;
        if (arr == 0)      src = Ah + (size_t)(bm + r) * K + k0 + c16 * 8;
        else if (arr == 1) src = Al + (size_t)(bm + r) * K + k0 + c16 * 8;
        else if (arr == 2) src = Bh + (size_t)(bn + r) * K + k0 + c16 * 8;
        else               src = Bl + (size_t)(bn + r) * K + k0 + c16 * 8;
        cp16(dst, src);
    }
}

__global__ void __launch_bounds__(256)
mma_gemm_kernel(const __nv_bfloat16* __restrict__ Ah,
                const __nv_bfloat16* __restrict__ Al,
                const __nv_bfloat16* __restrict__ Bh,
                const __nv_bfloat16* __restrict__ Bl,
                float* __restrict__ C, int M, int N, int K)
{
    extern __shared__ char smem[];
    const uint32_t sb = smem_u32(smem);

    const int tid  = threadIdx.x;
    const int wid  = tid >> 5;
    const int lane = tid & 31;
    const int wy   = wid >> 2;
    const int wx   = wid & 3;
    const int bm = blockIdx.y * BM;
    const int bn = blockIdx.x * BN;

    float acc[4][4][4];
#pragma unroll
    for (int mt = 0; mt < 4; mt++)
#pragma unroll
        for (int nt = 0; nt < 4; nt++)
#pragma unroll
            for (int e = 0; e < 4; e++) acc[mt][nt][e] = 0.f;

    const int a_row = wy * 64 + (lane & 15);
    const int a_kof = (lane >> 4) * 8;
    const int b_row = wx * 32 + (lane & 7);
    const int b_kof = ((lane >> 3) & 1) * 8;

    const int nk = K / BK;

    g_load_stage(sb, Ah, Al, Bh, Bl, bm, bn, 0, K, tid);
    CP_COMMIT();

    for (int i = 0; i < nk; i++) {
        const uint32_t st = sb + (i & 1) * STAGE_B;
        if (i + 1 < nk) {
            g_load_stage(sb + ((i + 1) & 1) * STAGE_B,
                         Ah, Al, Bh, Bl, bm, bn, (i + 1) * BK, K, tid);
            CP_COMMIT();
            CP_WAIT(1);
        } else {
            CP_WAIT(0);
        }
        __syncthreads();

        const uint32_t sAh = st;
        const uint32_t sAl = st + TILE_B;
        const uint32_t sBh = st + 2 * TILE_B;
        const uint32_t sBl = st + 3 * TILE_B;

#pragma unroll
        for (int ks = 0; ks < 2; ks++) {
            const int kk = ks * 16;
            uint32_t fah[4][4], fal[4][4], fbh[4][2], fbl[4][2];
#pragma unroll
            for (int mt = 0; mt < 4; mt++) {
                uint32_t off = (uint32_t)(a_row + mt * 16) * (PIT * 2)
                               + (uint32_t)(kk + a_kof) * 2;
                ldsm_x4(fah[mt], sAh + off);
                ldsm_x4(fal[mt], sAl + off);
            }
#pragma unroll
            for (int nt = 0; nt < 4; nt++) {
                uint32_t off = (uint32_t)(b_row + nt * 8) * (PIT * 2)
                               + (uint32_t)(kk + b_kof) * 2;
                ldsm_x2(fbh[nt], sBh + off);
                ldsm_x2(fbl[nt], sBl + off);
            }
#pragma unroll
            for (int mt = 0; mt < 4; mt++)
#pragma unroll
                for (int nt = 0; nt < 4; nt++) {
                    mma16816(acc[mt][nt], fah[mt], fbh[nt]);
                    mma16816(acc[mt][nt], fah[mt], fbl[nt]);
                    mma16816(acc[mt][nt], fal[mt], fbh[nt]);
                }
        }
        __syncthreads();
    }

    const int er = lane >> 2;
    const int ec = (lane & 3) * 2;
#pragma unroll
    for (int mt = 0; mt < 4; mt++) {
        const int r0 = bm + wy * 64 + mt * 16 + er;
#pragma unroll
        for (int nt = 0; nt < 4; nt++) {
            const int c0 = bn + wx * 32 + nt * 8 + ec;
            *(float2*)&C[(size_t)r0 * N + c0] =
                make_float2(acc[mt][nt][0], acc[mt][nt][1]);
            *(float2*)&C[(size_t)(r0 + 8) * N + c0] =
                make_float2(acc[mt][nt][2], acc[mt][nt][3]);
        }
    }
}

// ---------------------------------------------------------------------------
// Flash attention, HMMA bf16 hi/lo (3-pass QK^T + 3-pass PV), causal.
// CTA: 128 q-rows, 8 warps x 16 rows. K-tiles of 64, double-buffered.
// ---------------------------------------------------------------------------
#define FPITCH 272                 // bytes per smem row (128 bf16 + pad)
#define FQ_B   (128 * FPITCH)      // 34816 per Q array
#define FKV_A  (64 * FPITCH)       // 17408 per K/V array
#define SQH_O  0
#define SQL_O  FQ_B
#define SKV_O  (2 * FQ_B)
#define KV_STAGE_B (4 * FKV_A)     // kh,kl,vh,vl = 69632
#define FLASH_SMEM (2 * FQ_B + 2 * KV_STAGE_B)   // 208896

__device__ __forceinline__ void f_load_kv(
    uint32_t st, const __nv_bfloat16* __restrict__ Kh,
    const __nv_bfloat16* __restrict__ Kl, const __nv_bfloat16* __restrict__ Vh,
    const __nv_bfloat16* __restrict__ Vl, size_t base, int kb, int tid)
{
#pragma unroll
    for (int it = 0; it < 16; it++) {
        int c = tid + it * 256;          // 0..4095
        int arr = c >> 10;
        int r   = (c >> 4) & 63;
        int ch  = c & 15;
        uint32_t dst = st + arr * FKV_A + r * FPITCH + ch * 16;
        const __nv_bfloat16* src;
        size_t ge = base + (size_t)(kb + r) * D_DIM + ch * 8;
        if (arr == 0)      src = Kh + ge;
        else if (arr == 1) src = Kl + ge;
        else if (arr == 2) src = Vh + ge;
        else               src = Vl + ge;
        cp16(dst, src);
    }
}

__global__ void __launch_bounds__(256, 1)
flash_mma_kernel(const __nv_bfloat16* __restrict__ Qh,
                 const __nv_bfloat16* __restrict__ Ql,
                 const __nv_bfloat16* __restrict__ Kh,
                 const __nv_bfloat16* __restrict__ Kl,
                 const __nv_bfloat16* __restrict__ Vh,
                 const __nv_bfloat16* __restrict__ Vl,
                 float* __restrict__ Og)
{
    extern __shared__ char smc[];
    const uint32_t sb = smem_u32(smc);

    const int tid  = threadIdx.x;
    const int wid  = tid >> 5;
    const int lane = tid & 31;
    const int bh = blockIdx.x;
    const int b  = bh >> 4;
    const int h  = bh & 15;
    const int qt = (int)gridDim.y - 1 - (int)blockIdx.y;   // heavy tiles first
    const int q0 = qt * 128;
    const size_t base = (size_t)b * S_LEN * D_DIM + (size_t)h * HD;
    const int nkt = 2 * (qt + 1);

    // Prologue loads: Q (both arrays) + KV tile 0 -> one cp.async group
#pragma unroll
    for (int it = 0; it < 16; it++) {
        int c = tid + it * 256;          // 0..4095
        int arr = c >> 11;
        int r   = (c >> 4) & 127;
        int ch  = c & 15;
        uint32_t dst = sb + (arr ? SQL_O : SQH_O) + r * FPITCH + ch * 16;
        const __nv_bfloat16* src = (arr ? Ql : Qh)
                                   + base + (size_t)(q0 + r) * D_DIM + ch * 8;
        cp16(dst, src);
    }
    f_load_kv(sb + SKV_O, Kh, Kl, Vh, Vl, base, 0, tid);
    CP_COMMIT();

    const int wrow = wid * 16;
    float o[16][4];
#pragma unroll
    for (int nt = 0; nt < 16; nt++)
#pragma unroll
        for (int e = 0; e < 4; e++) o[nt][e] = 0.f;
    float m0 = -1e30f, m1 = -1e30f, l0 = 0.f, l1 = 0.f;
    const float sc = 0.08838834764831845f * 1.4426950408889634f; // scale*log2e
    const unsigned FULL = 0xffffffffu;

    for (int t = 0; t < nkt; t++) {
        const uint32_t st = sb + SKV_O + (t & 1) * KV_STAGE_B;
        if (t + 1 < nkt) {
            f_load_kv(sb + SKV_O + ((t + 1) & 1) * KV_STAGE_B,
                      Kh, Kl, Vh, Vl, base, (t + 1) * 64, tid);
            CP_COMMIT();
            CP_WAIT(1);
        } else {
            CP_WAIT(0);
        }
        __syncthreads();

        const uint32_t KHs = st;
        const uint32_t KLs = st + FKV_A;
        const uint32_t VHs = st + 2 * FKV_A;
        const uint32_t VLs = st + 3 * FKV_A;
        const int kb = t * 64;

        // ---- S = Q K^T (3-pass) ----
        float s[8][4];
#pragma unroll
        for (int nt = 0; nt < 8; nt++)
#pragma unroll
            for (int e = 0; e < 4; e++) s[nt][e] = 0.f;

#pragma unroll
        for (int kk = 0; kk < 8; kk++) {
            uint32_t aoff = (uint32_t)(wrow + (lane & 15)) * FPITCH
                            + (uint32_t)(kk * 16 + (lane >> 4) * 8) * 2;
            uint32_t ah[4], al[4];
            ldsm_x4(ah, sb + SQH_O + aoff);
            ldsm_x4(al, sb + SQL_O + aoff);
#pragma unroll
            for (int np = 0; np < 4; np++) {
                uint32_t boff = (uint32_t)(np * 16 + (lane & 7) + ((lane >> 4) << 3)) * FPITCH
                                + (uint32_t)(kk * 16 + (((lane >> 3) & 1) << 3)) * 2;
                uint32_t bh4[4], bl4[4];
                ldsm_x4(bh4, KHs + boff);
                ldsm_x4(bl4, KLs + boff);
                mma16816(s[2 * np],     ah, bh4);
                mma16816(s[2 * np + 1], ah, bh4 + 2);
                mma16816(s[2 * np],     ah, bl4);
                mma16816(s[2 * np + 1], ah, bl4 + 2);
                mma16816(s[2 * np],     al, bh4);
                mma16816(s[2 * np + 1], al, bh4 + 2);
            }
        }

        // ---- mask + online softmax ----
        if (t + 2 >= nkt) {
            const int row0 = q0 + wrow + (lane >> 2);
            const int row1 = row0 + 8;
            const int cbse = kb + ((lane & 3) << 1);
#pragma unroll
            for (int nt = 0; nt < 8; nt++) {
                const int c = cbse + nt * 8;
                if (c     > row0) s[nt][0] = -1e30f;
                if (c + 1 > row0) s[nt][1] = -1e30f;
                if (c     > row1) s[nt][2] = -1e30f;
                if (c + 1 > row1) s[nt][3] = -1e30f;
            }
        }
        float mx0 = -1e30f, mx1 = -1e30f;
#pragma unroll
        for (int nt = 0; nt < 8; nt++) {
            mx0 = fmaxf(mx0, fmaxf(s[nt][0], s[nt][1]));
            mx1 = fmaxf(mx1, fmaxf(s[nt][2], s[nt][3]));
        }
        mx0 = fmaxf(mx0, __shfl_xor_sync(FULL, mx0, 1));
        mx0 = fmaxf(mx0, __shfl_xor_sync(FULL, mx0, 2));
        mx1 = fmaxf(mx1, __shfl_xor_sync(FULL, mx1, 1));
        mx1 = fmaxf(mx1, __shfl_xor_sync(FULL, mx1, 2));
        const float mn0 = fmaxf(m0, mx0);
        const float mn1 = fmaxf(m1, mx1);
        const float cr0 = ex2((m0 - mn0) * sc);
        const float cr1 = ex2((m1 - mn1) * sc);
        m0 = mn0; m1 = mn1;
        float rs0 = 0.f, rs1 = 0.f;
#pragma unroll
        for (int nt = 0; nt < 8; nt++) {
            s[nt][0] = ex2((s[nt][0] - mn0) * sc);
            s[nt][1] = ex2((s[nt][1] - mn0) * sc);
            s[nt][2] = ex2((s[nt][2] - mn1) * sc);
            s[nt][3] = ex2((s[nt][3] - mn1) * sc);
            rs0 += s[nt][0] + s[nt][1];
            rs1 += s[nt][2] + s[nt][3];
        }
        rs0 += __shfl_xor_sync(FULL, rs0, 1);
        rs0 += __shfl_xor_sync(FULL, rs0, 2);
        rs1 += __shfl_xor_sync(FULL, rs1, 1);
        rs1 += __shfl_xor_sync(FULL, rs1, 2);
        l0 = l0 * cr0 + rs0;
        l1 = l1 * cr1 + rs1;
#pragma unroll
        for (int nt = 0; nt < 16; nt++) {
            o[nt][0] *= cr0; o[nt][1] *= cr0;
            o[nt][2] *= cr1; o[nt][3] *= cr1;
        }

        // ---- P -> bf16 hi/lo a-fragments ----
        uint32_t ph[4][4], pl[4][4];
#pragma unroll
        for (int j = 0; j < 4; j++) {
            ph[j][0] = pk_hi(s[2 * j][0],     s[2 * j][1]);
            ph[j][1] = pk_hi(s[2 * j][2],     s[2 * j][3]);
            ph[j][2] = pk_hi(s[2 * j + 1][0], s[2 * j + 1][1]);
            ph[j][3] = pk_hi(s[2 * j + 1][2], s[2 * j + 1][3]);
            pl[j][0] = pk_lo(s[2 * j][0],     s[2 * j][1],     ph[j][0]);
            pl[j][1] = pk_lo(s[2 * j][2],     s[2 * j][3],     ph[j][1]);
            pl[j][2] = pk_lo(s[2 * j + 1][0], s[2 * j + 1][1], ph[j][2]);
            pl[j][3] = pk_lo(s[2 * j + 1][2], s[2 * j + 1][3], ph[j][3]);
        }

        // ---- O += P V (3-pass), V b-frags via ldmatrix.trans ----
#pragma unroll
        for (int j = 0; j < 4; j++) {
#pragma unroll
            for (int nd = 0; nd < 8; nd++) {
                uint32_t boff = (uint32_t)(j * 16 + (lane & 7) + (((lane >> 3) & 1) << 3)) * FPITCH
                                + (uint32_t)(nd * 16 + ((lane >> 4) << 3)) * 2;
                uint32_t vh4[4], vl4[4];
                ldsm_x4_t(vh4, VHs + boff);
                ldsm_x4_t(vl4, VLs + boff);
                mma16816(o[2 * nd],     ph[j], vh4);
                mma16816(o[2 * nd + 1], ph[j], vh4 + 2);
                mma16816(o[2 * nd],     ph[j], vl4);
                mma16816(o[2 * nd + 1], ph[j], vl4 + 2);
                mma16816(o[2 * nd],     pl[j], vh4);
                mma16816(o[2 * nd + 1], pl[j], vh4 + 2);
            }
        }
        __syncthreads();
    }

    // ---- normalize + write ctx ----
    const float i0 = 1.f / l0;
    const float i1 = 1.f / l1;
    const int r0 = q0 + wrow + (lane >> 2);
    const int r1 = r0 + 8;
#pragma unroll
    for (int nt = 0; nt < 16; nt++) {
        const int col = nt * 8 + ((lane & 3) << 1);
        *(float2*)&Og[base + (size_t)r0 * D_DIM + col] =
            make_float2(o[nt][0] * i0, o[nt][1] * i0);
        *(float2*)&Og[base + (size_t)r1 * D_DIM + col] =
            make_float2(o[nt][2] * i1, o[nt][3] * i1);
    }
}

// ---------------------------------------------------------------------------
// Launcher
// ---------------------------------------------------------------------------
extern "C" void kernel_launch(void* const* d_in, const int* in_sizes, int n_in,
                              void* d_out, int out_size)
{
    const float* x  = (const float*)d_in[0];
    const float* Wq = (const float*)d_in[1];
    const float* Wk = (const float*)d_in[2];
    const float* Wv = (const float*)d_in[3];
    const float* Wo = (const float*)d_in[4];
    float* out = (float*)d_out;

    float *q, *k, *v, *ctx;
    __nv_bfloat16 *ahi, *alo, *whi, *wlo, *qh, *ql, *kh, *kl, *vh, *vl;
    cudaGetSymbolAddress((void**)&q,   g_q);
    cudaGetSymbolAddress((void**)&k,   g_k);
    cudaGetSymbolAddress((void**)&v,   g_v);
    cudaGetSymbolAddress((void**)&ctx, g_ctx);
    cudaGetSymbolAddress((void**)&ahi, g_ahi);
    cudaGetSymbolAddress((void**)&alo, g_alo);
    cudaGetSymbolAddress((void**)&whi, g_whi);
    cudaGetSymbolAddress((void**)&wlo, g_wlo);
    cudaGetSymbolAddress((void**)&qh,  g_qh);
    cudaGetSymbolAddress((void**)&ql,  g_ql);
    cudaGetSymbolAddress((void**)&kh,  g_kh);
    cudaGetSymbolAddress((void**)&kl,  g_kl);
    cudaGetSymbolAddress((void**)&vh,  g_vh);
    cudaGetSymbolAddress((void**)&vl,  g_vl);

    cudaFuncSetAttribute(mma_gemm_kernel,
                         cudaFuncAttributeMaxDynamicSharedMemorySize, GEMM_SMEM);
    cudaFuncSetAttribute(flash_mma_kernel,
                         cudaFuncAttributeMaxDynamicSharedMemorySize, FLASH_SMEM);

    const int nx4 = (M_ROWS * D_DIM) / 4;
    const int nw4 = (D_DIM * D_DIM) / 4;
    dim3 ggrid(D_DIM / BN, M_ROWS / BM);

    // x -> bf16 hi/lo
    split_kernel<<<(nx4 + 255) / 256, 256>>>(x, ahi, alo, nx4);

    // Q/K/V projections (fp32 outputs)
    split_kernel<<<(nw4 + 255) / 256, 256>>>(Wq, whi, wlo, nw4);
    mma_gemm_kernel<<<ggrid, 256, GEMM_SMEM>>>(ahi, alo, whi, wlo, q,
                                               M_ROWS, D_DIM, D_DIM);
    split_kernel<<<(nw4 + 255) / 256, 256>>>(Wk, whi, wlo, nw4);
    mma_gemm_kernel<<<ggrid, 256, GEMM_SMEM>>>(ahi, alo, whi, wlo, k,
                                               M_ROWS, D_DIM, D_DIM);
    split_kernel<<<(nw4 + 255) / 256, 256>>>(Wv, whi, wlo, nw4);
    mma_gemm_kernel<<<ggrid, 256, GEMM_SMEM>>>(ahi, alo, whi, wlo, v,
                                               M_ROWS, D_DIM, D_DIM);

    // RoPE + split to bf16 hi/lo (q,k); plain split (v)
    const int rope_threads = M_ROWS * (D_DIM / 2);
    rope_split_kernel<<<(rope_threads + 255) / 256, 256>>>(q, qh, ql);
    rope_split_kernel<<<(rope_threads + 255) / 256, 256>>>(k, kh, kl);
    split_kernel<<<(nx4 + 255) / 256, 256>>>(v, vh, vl, nx4);

    // Flash attention (HMMA) -> ctx
    dim3 flash_grid(B_SZ * H_NUM, S_LEN / 128);   // (32, 16)
    flash_mma_kernel<<<flash_grid, 256, FLASH_SMEM>>>(qh, ql, kh, kl, vh, vl, ctx);

    // Output projection
    split_kernel<<<(nx4 + 255) / 256, 256>>>(ctx, ahi, alo, nx4);
    split_kernel<<<(nw4 + 255) / 256, 256>>>(Wo, whi, wlo, nw4);
    mma_gemm_kernel<<<ggrid, 256, GEMM_SMEM>>>(ahi, alo, whi, wlo, out,
                                               M_ROWS, D_DIM, D_DIM);
}

// round 6
// speedup vs baseline: 2.7744x; 1.0824x over previous
#include <cuda_runtime.h>
#include <cuda_bf16.h>
#include <math.h>
#include <cstdint>

// Problem constants
#define B_SZ   2
#define S_LEN  2048
#define D_DIM  2048
#define H_NUM  16
#define HD     128
#define M_ROWS (B_SZ * S_LEN)   // 4096

// ---------------------------------------------------------------------------
// Scratch (static device globals)
// ---------------------------------------------------------------------------
__device__ __nv_bfloat16 g_ahi[M_ROWS * D_DIM];       // x hi, later ctx hi
__device__ __nv_bfloat16 g_alo[M_ROWS * D_DIM];       // x lo, later ctx lo
__device__ __nv_bfloat16 g_w3hi[3 * D_DIM * D_DIM];   // [Wq;Wk;Wv] hi
__device__ __nv_bfloat16 g_w3lo[3 * D_DIM * D_DIM];   // [Wq;Wk;Wv] lo
__device__ __nv_bfloat16 g_whi[D_DIM * D_DIM];        // Wo hi
__device__ __nv_bfloat16 g_wlo[D_DIM * D_DIM];        // Wo lo
__device__ __nv_bfloat16 g_qh [M_ROWS * D_DIM];
__device__ __nv_bfloat16 g_ql [M_ROWS * D_DIM];
__device__ __nv_bfloat16 g_kh [M_ROWS * D_DIM];
__device__ __nv_bfloat16 g_kl [M_ROWS * D_DIM];
__device__ __nv_bfloat16 g_vh [M_ROWS * D_DIM];
__device__ __nv_bfloat16 g_vl [M_ROWS * D_DIM];
__device__ float2 g_tab[S_LEN * 64];                  // rope (cos,sin) table

// ---------------------------------------------------------------------------
// PTX helpers
// ---------------------------------------------------------------------------
__device__ __forceinline__ uint32_t smem_u32(const void* p) {
    uint32_t a;
    asm("{ .reg .u64 t; cvta.to.shared.u64 t, %1; cvt.u32.u64 %0, t; }"
        : "=r"(a) : "l"(p));
    return a;
}
__device__ __forceinline__ void cp16(uint32_t s, const void* g) {
    asm volatile("cp.async.cg.shared.global [%0], [%1], 16;" :: "r"(s), "l"(g));
}
#define CP_COMMIT() asm volatile("cp.async.commit_group;" ::: "memory")
#define CP_WAIT(n)  asm volatile("cp.async.wait_group %0;" :: "n"(n) : "memory")

__device__ __forceinline__ void ldsm_x4(uint32_t* r, uint32_t addr) {
    asm volatile("ldmatrix.sync.aligned.m8n8.x4.shared.b16 {%0,%1,%2,%3}, [%4];"
                 : "=r"(r[0]), "=r"(r[1]), "=r"(r[2]), "=r"(r[3]) : "r"(addr));
}
__device__ __forceinline__ void ldsm_x4_t(uint32_t* r, uint32_t addr) {
    asm volatile("ldmatrix.sync.aligned.m8n8.x4.trans.shared.b16 {%0,%1,%2,%3}, [%4];"
                 : "=r"(r[0]), "=r"(r[1]), "=r"(r[2]), "=r"(r[3]) : "r"(addr));
}
__device__ __forceinline__ void ldsm_x2(uint32_t* r, uint32_t addr) {
    asm volatile("ldmatrix.sync.aligned.m8n8.x2.shared.b16 {%0,%1}, [%2];"
                 : "=r"(r[0]), "=r"(r[1]) : "r"(addr));
}
__device__ __forceinline__ void mma16816(float* d, const uint32_t* a,
                                         const uint32_t* b) {
    asm volatile(
        "mma.sync.aligned.m16n8k16.row.col.f32.bf16.bf16.f32 "
        "{%0,%1,%2,%3}, {%4,%5,%6,%7}, {%8,%9}, {%0,%1,%2,%3};"
        : "+f"(d[0]), "+f"(d[1]), "+f"(d[2]), "+f"(d[3])
        : "r"(a[0]), "r"(a[1]), "r"(a[2]), "r"(a[3]), "r"(b[0]), "r"(b[1]));
}
__device__ __forceinline__ float ex2(float x) {
    float y;
    asm("ex2.approx.ftz.f32 %0, %1;" : "=f"(y) : "f"(x));
    return y;
}
__device__ __forceinline__ uint32_t pk_hi(float a, float b) {
    __nv_bfloat162 t = __floats2bfloat162_rn(a, b);
    return *(uint32_t*)&t;
}
__device__ __forceinline__ uint32_t pk_lo(float a, float b, uint32_t hi) {
    __nv_bfloat162 h = *(__nv_bfloat162*)&hi;
    return pk_hi(a - __bfloat162float(h.x), b - __bfloat162float(h.y));
}

// ---------------------------------------------------------------------------
// RoPE table: (cos, sin) for (s, pair i)  — same formula as reference
// ---------------------------------------------------------------------------
__global__ void tab_kernel(float2* __restrict__ T)
{
    int idx = blockIdx.x * blockDim.x + threadIdx.x;
    if (idx >= S_LEN * 64) return;
    int s = idx >> 6;
    int i = idx & 63;
    float inv = powf(10000.f, -(float)(2 * i) / 128.f);
    float ang = (float)s * inv;
    float sv, cv;
    sincosf(ang, &sv, &cv);
    T[idx] = make_float2(cv, sv);
}

// ---------------------------------------------------------------------------
// split: fp32 -> (hi bf16, lo bf16)
// ---------------------------------------------------------------------------
__global__ void split_kernel(const float* __restrict__ X,
                             __nv_bfloat16* __restrict__ H,
                             __nv_bfloat16* __restrict__ L, int n4)
{
    int i = blockIdx.x * blockDim.x + threadIdx.x;
    if (i >= n4) return;
    float4 v = ((const float4*)X)[i];
    uint32_t h0 = pk_hi(v.x, v.y), h1 = pk_hi(v.z, v.w);
    uint32_t l0 = pk_lo(v.x, v.y, h0), l1 = pk_lo(v.z, v.w, h1);
    ((uint2*)H)[i] = make_uint2(h0, h1);
    ((uint2*)L)[i] = make_uint2(l0, l1);
}

// ---------------------------------------------------------------------------
// HMMA bf16 split GEMM core. MODE 0: fp32 C out. MODE 1: fused QKV epilogue
// (rope+split for q/k, split for v) writing bf16 hi/lo pairs.
// ---------------------------------------------------------------------------
#define BM 128
#define BN 128
#define BK 32
#define PIT 40
#define TILE_B (BM * PIT * 2)
#define STAGE_B (4 * TILE_B)
#define GEMM_SMEM (2 * STAGE_B)

__device__ __forceinline__ void g_load_stage(
    uint32_t st, const __nv_bfloat16* __restrict__ Ah,
    const __nv_bfloat16* __restrict__ Al, const __nv_bfloat16* __restrict__ Bh,
    const __nv_bfloat16* __restrict__ Bl, int bm, int bn, int k0, int K, int tid)
{
#pragma unroll
    for (int it = 0; it < 8; it++) {
        int c = tid + it * 256;
        int arr = c >> 9;
        int r   = (c & 511) >> 2;
        int c16 = c & 3;
        uint32_t dst = st + arr * TILE_B + r * (PIT * 2) + c16 * 16;
        const __nv_bfloat16* src;
        if (arr == 0)      src = Ah + (size_t)(bm + r) * K + k0 + c16 * 8;
        else if (arr == 1) src = Al + (size_t)(bm + r) * K + k0 + c16 * 8;
        else if (arr == 2) src = Bh + (size_t)(bn + r) * K + k0 + c16 * 8;
        else               src = Bl + (size_t)(bn + r) * K + k0 + c16 * 8;
        cp16(dst, src);
    }
}

template <int MODE>
__global__ void __launch_bounds__(256)
mma_gemm_kernel(const __nv_bfloat16* __restrict__ Ah,
                const __nv_bfloat16* __restrict__ Al,
                const __nv_bfloat16* __restrict__ Bh,
                const __nv_bfloat16* __restrict__ Bl,
                float* __restrict__ C,
                __nv_bfloat16* __restrict__ QH, __nv_bfloat16* __restrict__ QL,
                __nv_bfloat16* __restrict__ KH, __nv_bfloat16* __restrict__ KL,
                __nv_bfloat16* __restrict__ VH, __nv_bfloat16* __restrict__ VL,
                const float2* __restrict__ tab,
                int M, int N, int K)
{
    extern __shared__ char smem[];
    const uint32_t sb = smem_u32(smem);

    const int tid  = threadIdx.x;
    const int wid  = tid >> 5;
    const int lane = tid & 31;
    const int wy   = wid >> 2;
    const int wx   = wid & 3;
    const int bm = blockIdx.y * BM;
    const int bn = blockIdx.x * BN;

    float acc[4][4][4];
#pragma unroll
    for (int mt = 0; mt < 4; mt++)
#pragma unroll
        for (int nt = 0; nt < 4; nt++)
#pragma unroll
            for (int e = 0; e < 4; e++) acc[mt][nt][e] = 0.f;

    const int a_row = wy * 64 + (lane & 15);
    const int a_kof = (lane >> 4) * 8;
    const int b_row = wx * 32 + (lane & 7);
    const int b_kof = ((lane >> 3) & 1) * 8;

    const int nk = K / BK;

    g_load_stage(sb, Ah, Al, Bh, Bl, bm, bn, 0, K, tid);
    CP_COMMIT();

    for (int i = 0; i < nk; i++) {
        const uint32_t st = sb + (i & 1) * STAGE_B;
        if (i + 1 < nk) {
            g_load_stage(sb + ((i + 1) & 1) * STAGE_B,
                         Ah, Al, Bh, Bl, bm, bn, (i + 1) * BK, K, tid);
            CP_COMMIT();
            CP_WAIT(1);
        } else {
            CP_WAIT(0);
        }
        __syncthreads();

        const uint32_t sAh = st;
        const uint32_t sAl = st + TILE_B;
        const uint32_t sBh = st + 2 * TILE_B;
        const uint32_t sBl = st + 3 * TILE_B;

#pragma unroll
        for (int ks = 0; ks < 2; ks++) {
            const int kk = ks * 16;
            uint32_t fah[4][4], fal[4][4], fbh[4][2], fbl[4][2];
#pragma unroll
            for (int mt = 0; mt < 4; mt++) {
                uint32_t off = (uint32_t)(a_row + mt * 16) * (PIT * 2)
                               + (uint32_t)(kk + a_kof) * 2;
                ldsm_x4(fah[mt], sAh + off);
                ldsm_x4(fal[mt], sAl + off);
            }
#pragma unroll
            for (int nt = 0; nt < 4; nt++) {
                uint32_t off = (uint32_t)(b_row + nt * 8) * (PIT * 2)
                               + (uint32_t)(kk + b_kof) * 2;
                ldsm_x2(fbh[nt], sBh + off);
                ldsm_x2(fbl[nt], sBl + off);
            }
#pragma unroll
            for (int mt = 0; mt < 4; mt++)
#pragma unroll
                for (int nt = 0; nt < 4; nt++) {
                    mma16816(acc[mt][nt], fah[mt], fbh[nt]);
                    mma16816(acc[mt][nt], fah[mt], fbl[nt]);
                    mma16816(acc[mt][nt], fal[mt], fbh[nt]);
                }
        }
        __syncthreads();
    }

    const int er = lane >> 2;
    const int ec = (lane & 3) * 2;

    if (MODE == 0) {
#pragma unroll
        for (int mt = 0; mt < 4; mt++) {
            const int r0 = bm + wy * 64 + mt * 16 + er;
#pragma unroll
            for (int nt = 0; nt < 4; nt++) {
                const int c0 = bn + wx * 32 + nt * 8 + ec;
                *(float2*)&C[(size_t)r0 * N + c0] =
                    make_float2(acc[mt][nt][0], acc[mt][nt][1]);
                *(float2*)&C[(size_t)(r0 + 8) * N + c0] =
                    make_float2(acc[mt][nt][2], acc[mt][nt][3]);
            }
        }
    } else {
        // Fused QKV epilogue. N = 6144 over [Wq;Wk;Wv]; sel is CTA-uniform.
        const int sel = bn >> 11;                 // 0=q, 1=k, 2=v
        __nv_bfloat16* H = (sel == 0) ? QH : (sel == 1) ? KH : VH;
        __nv_bfloat16* L = (sel == 0) ? QL : (sel == 1) ? KL : VL;
#pragma unroll
        for (int mt = 0; mt < 4; mt++) {
            const int r0 = bm + wy * 64 + mt * 16 + er;
            const int r1 = r0 + 8;
#pragma unroll
            for (int nt = 0; nt < 4; nt++) {
                const int c = (bn + wx * 32 + nt * 8 + ec) & 2047;
                float a0 = acc[mt][nt][0], a1 = acc[mt][nt][1];
                float b0 = acc[mt][nt][2], b1 = acc[mt][nt][3];
                if (sel < 2) {
                    const int pair = (c & 127) >> 1;
                    float2 t0 = tab[(r0 & (S_LEN - 1)) * 64 + pair];
                    float2 t1 = tab[(r1 & (S_LEN - 1)) * 64 + pair];
                    float rx0 = a0 * t0.x - a1 * t0.y;
                    float ry0 = a0 * t0.y + a1 * t0.x;
                    float rx1 = b0 * t1.x - b1 * t1.y;
                    float ry1 = b0 * t1.y + b1 * t1.x;
                    a0 = rx0; a1 = ry0; b0 = rx1; b1 = ry1;
                }
                uint32_t h0 = pk_hi(a0, a1), l0 = pk_lo(a0, a1, h0);
                uint32_t h1 = pk_hi(b0, b1), l1 = pk_lo(b0, b1, h1);
                const size_t p0 = ((size_t)r0 * D_DIM + c) >> 1;
                const size_t p1 = ((size_t)r1 * D_DIM + c) >> 1;
                ((uint32_t*)H)[p0] = h0;
                ((uint32_t*)L)[p0] = l0;
                ((uint32_t*)H)[p1] = h1;
                ((uint32_t*)L)[p1] = l1;
            }
        }
    }
}

// ---------------------------------------------------------------------------
// Flash attention, HMMA bf16 hi/lo (3-pass QK^T + 3-pass PV), causal.
// Epilogue writes ctx as bf16 hi/lo (feeds out-projection directly).
// ---------------------------------------------------------------------------
#define FPITCH 272
#define FQ_B   (128 * FPITCH)
#define FKV_A  (64 * FPITCH)
#define SQH_O  0
#define SQL_O  FQ_B
#define SKV_O  (2 * FQ_B)
#define KV_STAGE_B (4 * FKV_A)
#define FLASH_SMEM (2 * FQ_B + 2 * KV_STAGE_B)

__device__ __forceinline__ void f_load_kv(
    uint32_t st, const __nv_bfloat16* __restrict__ Kh,
    const __nv_bfloat16* __restrict__ Kl, const __nv_bfloat16* __restrict__ Vh,
    const __nv_bfloat16* __restrict__ Vl, size_t base, int kb, int tid)
{
#pragma unroll
    for (int it = 0; it < 16; it++) {
        int c = tid + it * 256;
        int arr = c >> 10;
        int r   = (c >> 4) & 63;
        int ch  = c & 15;
        uint32_t dst = st + arr * FKV_A + r * FPITCH + ch * 16;
        const __nv_bfloat16* src;
        size_t ge = base + (size_t)(kb + r) * D_DIM + ch * 8;
        if (arr == 0)      src = Kh + ge;
        else if (arr == 1) src = Kl + ge;
        else if (arr == 2) src = Vh + ge;
        else               src = Vl + ge;
        cp16(dst, src);
    }
}

__global__ void __launch_bounds__(256, 1)
flash_mma_kernel(const __nv_bfloat16* __restrict__ Qh,
                 const __nv_bfloat16* __restrict__ Ql,
                 const __nv_bfloat16* __restrict__ Kh,
                 const __nv_bfloat16* __restrict__ Kl,
                 const __nv_bfloat16* __restrict__ Vh,
                 const __nv_bfloat16* __restrict__ Vl,
                 __nv_bfloat16* __restrict__ OH,
                 __nv_bfloat16* __restrict__ OL)
{
    extern __shared__ char smc[];
    const uint32_t sb = smem_u32(smc);

    const int tid  = threadIdx.x;
    const int wid  = tid >> 5;
    const int lane = tid & 31;
    const int bh = blockIdx.x;
    const int b  = bh >> 4;
    const int h  = bh & 15;
    const int qt = (int)gridDim.y - 1 - (int)blockIdx.y;
    const int q0 = qt * 128;
    const size_t base = (size_t)b * S_LEN * D_DIM + (size_t)h * HD;
    const int nkt = 2 * (qt + 1);

#pragma unroll
    for (int it = 0; it < 16; it++) {
        int c = tid + it * 256;
        int arr = c >> 11;
        int r   = (c >> 4) & 127;
        int ch  = c & 15;
        uint32_t dst = sb + (arr ? SQL_O : SQH_O) + r * FPITCH + ch * 16;
        const __nv_bfloat16* src = (arr ? Ql : Qh)
                                   + base + (size_t)(q0 + r) * D_DIM + ch * 8;
        cp16(dst, src);
    }
    f_load_kv(sb + SKV_O, Kh, Kl, Vh, Vl, base, 0, tid);
    CP_COMMIT();

    const int wrow = wid * 16;
    float o[16][4];
#pragma unroll
    for (int nt = 0; nt < 16; nt++)
#pragma unroll
        for (int e = 0; e < 4; e++) o[nt][e] = 0.f;
    float m0 = -1e30f, m1 = -1e30f, l0 = 0.f, l1 = 0.f;
    const float sc = 0.08838834764831845f * 1.4426950408889634f;
    const unsigned FULL = 0xffffffffu;

    for (int t = 0; t < nkt; t++) {
        const uint32_t st = sb + SKV_O + (t & 1) * KV_STAGE_B;
        if (t + 1 < nkt) {
            f_load_kv(sb + SKV_O + ((t + 1) & 1) * KV_STAGE_B,
                      Kh, Kl, Vh, Vl, base, (t + 1) * 64, tid);
            CP_COMMIT();
            CP_WAIT(1);
        } else {
            CP_WAIT(0);
        }
        __syncthreads();

        const uint32_t KHs = st;
        const uint32_t KLs = st + FKV_A;
        const uint32_t VHs = st + 2 * FKV_A;
        const uint32_t VLs = st + 3 * FKV_A;
        const int kb = t * 64;

        float s[8][4];
#pragma unroll
        for (int nt = 0; nt < 8; nt++)
#pragma unroll
            for (int e = 0; e < 4; e++) s[nt][e] = 0.f;

#pragma unroll
        for (int kk = 0; kk < 8; kk++) {
            uint32_t aoff = (uint32_t)(wrow + (lane & 15)) * FPITCH
                            + (uint32_t)(kk * 16 + (lane >> 4) * 8) * 2;
            uint32_t ah[4], al[4];
            ldsm_x4(ah, sb + SQH_O + aoff);
            ldsm_x4(al, sb + SQL_O + aoff);
#pragma unroll
            for (int np = 0; np < 4; np++) {
                uint32_t boff = (uint32_t)(np * 16 + (lane & 7) + ((lane >> 4) << 3)) * FPITCH
                                + (uint32_t)(kk * 16 + (((lane >> 3) & 1) << 3)) * 2;
                uint32_t bh4[4], bl4[4];
                ldsm_x4(bh4, KHs + boff);
                ldsm_x4(bl4, KLs + boff);
                mma16816(s[2 * np],     ah, bh4);
                mma16816(s[2 * np + 1], ah, bh4 + 2);
                mma16816(s[2 * np],     ah, bl4);
                mma16816(s[2 * np + 1], ah, bl4 + 2);
                mma16816(s[2 * np],     al, bh4);
                mma16816(s[2 * np + 1], al, bh4 + 2);
            }
        }

        if (t + 2 >= nkt) {
            const int row0 = q0 + wrow + (lane >> 2);
            const int row1 = row0 + 8;
            const int cbse = kb + ((lane & 3) << 1);
#pragma unroll
            for (int nt = 0; nt < 8; nt++) {
                const int c = cbse + nt * 8;
                if (c     > row0) s[nt][0] = -1e30f;
                if (c + 1 > row0) s[nt][1] = -1e30f;
                if (c     > row1) s[nt][2] = -1e30f;
                if (c + 1 > row1) s[nt][3] = -1e30f;
            }
        }
        float mx0 = -1e30f, mx1 = -1e30f;
#pragma unroll
        for (int nt = 0; nt < 8; nt++) {
            mx0 = fmaxf(mx0, fmaxf(s[nt][0], s[nt][1]));
            mx1 = fmaxf(mx1, fmaxf(s[nt][2], s[nt][3]));
        }
        mx0 = fmaxf(mx0, __shfl_xor_sync(FULL, mx0, 1));
        mx0 = fmaxf(mx0, __shfl_xor_sync(FULL, mx0, 2));
        mx1 = fmaxf(mx1, __shfl_xor_sync(FULL, mx1, 1));
        mx1 = fmaxf(mx1, __shfl_xor_sync(FULL, mx1, 2));
        const float mn0 = fmaxf(m0, mx0);
        const float mn1 = fmaxf(m1, mx1);
        const float cr0 = ex2((m0 - mn0) * sc);
        const float cr1 = ex2((m1 - mn1) * sc);
        m0 = mn0; m1 = mn1;
        float rs0 = 0.f, rs1 = 0.f;
#pragma unroll
        for (int nt = 0; nt < 8; nt++) {
            s[nt][0] = ex2((s[nt][0] - mn0) * sc);
            s[nt][1] = ex2((s[nt][1] - mn0) * sc);
            s[nt][2] = ex2((s[nt][2] - mn1) * sc);
            s[nt][3] = ex2((s[nt][3] - mn1) * sc);
            rs0 += s[nt][0] + s[nt][1];
            rs1 += s[nt][2] + s[nt][3];
        }
        rs0 += __shfl_xor_sync(FULL, rs0, 1);
        rs0 += __shfl_xor_sync(FULL, rs0, 2);
        rs1 += __shfl_xor_sync(FULL, rs1, 1);
        rs1 += __shfl_xor_sync(FULL, rs1, 2);
        l0 = l0 * cr0 + rs0;
        l1 = l1 * cr1 + rs1;
#pragma unroll
        for (int nt = 0; nt < 16; nt++) {
            o[nt][0] *= cr0; o[nt][1] *= cr0;
            o[nt][2] *= cr1; o[nt][3] *= cr1;
        }

        uint32_t ph[4][4], pl[4][4];
#pragma unroll
        for (int j = 0; j < 4; j++) {
            ph[j][0] = pk_hi(s[2 * j][0],     s[2 * j][1]);
            ph[j][1] = pk_hi(s[2 * j][2],     s[2 * j][3]);
            ph[j][2] = pk_hi(s[2 * j + 1][0], s[2 * j + 1][1]);
            ph[j][3] = pk_hi(s[2 * j + 1][2], s[2 * j + 1][3]);
            pl[j][0] = pk_lo(s[2 * j][0],     s[2 * j][1],     ph[j][0]);
            pl[j][1] = pk_lo(s[2 * j][2],     s[2 * j][3],     ph[j][1]);
            pl[j][2] = pk_lo(s[2 * j + 1][0], s[2 * j + 1][1], ph[j][2]);
            pl[j][3] = pk_lo(s[2 * j + 1][2], s[2 * j + 1][3], ph[j][3]);
        }

#pragma unroll
        for (int j = 0; j < 4; j++) {
#pragma unroll
            for (int nd = 0; nd < 8; nd++) {
                uint32_t boff = (uint32_t)(j * 16 + (lane & 7) + (((lane >> 3) & 1) << 3)) * FPITCH
                                + (uint32_t)(nd * 16 + ((lane >> 4) << 3)) * 2;
                uint32_t vh4[4], vl4[4];
                ldsm_x4_t(vh4, VHs + boff);
                ldsm_x4_t(vl4, VLs + boff);
                mma16816(o[2 * nd],     ph[j], vh4);
                mma16816(o[2 * nd + 1], ph[j], vh4 + 2);
                mma16816(o[2 * nd],     ph[j], vl4);
                mma16816(o[2 * nd + 1], ph[j], vl4 + 2);
                mma16816(o[2 * nd],     pl[j], vh4);
                mma16816(o[2 * nd + 1], pl[j], vh4 + 2);
            }
        }
        __syncthreads();
    }

    // normalize + write ctx bf16 hi/lo
    const float i0 = 1.f / l0;
    const float i1 = 1.f / l1;
    const int r0 = q0 + wrow + (lane >> 2);
    const int r1 = r0 + 8;
#pragma unroll
    for (int nt = 0; nt < 16; nt++) {
        const int col = nt * 8 + ((lane & 3) << 1);
        float a0 = o[nt][0] * i0, a1 = o[nt][1] * i0;
        float b0 = o[nt][2] * i1, b1 = o[nt][3] * i1;
        uint32_t h0 = pk_hi(a0, a1), L0 = pk_lo(a0, a1, h0);
        uint32_t h1 = pk_hi(b0, b1), L1 = pk_lo(b0, b1, h1);
        const size_t p0 = (base + (size_t)r0 * D_DIM + col) >> 1;
        const size_t p1 = (base + (size_t)r1 * D_DIM + col) >> 1;
        ((uint32_t*)OH)[p0] = h0;
        ((uint32_t*)OL)[p0] = L0;
        ((uint32_t*)OH)[p1] = h1;
        ((uint32_t*)OL)[p1] = L1;
    }
}

// ---------------------------------------------------------------------------
// Launcher
// ---------------------------------------------------------------------------
extern "C" void kernel_launch(void* const* d_in, const int* in_sizes, int n_in,
                              void* d_out, int out_size)
{
    const float* x  = (const float*)d_in[0];
    const float* Wq = (const float*)d_in[1];
    const float* Wk = (const float*)d_in[2];
    const float* Wv = (const float*)d_in[3];
    const float* Wo = (const float*)d_in[4];
    float* out = (float*)d_out;

    __nv_bfloat16 *ahi, *alo, *w3hi, *w3lo, *whi, *wlo, *qh, *ql, *kh, *kl, *vh, *vl;
    float2* tab;
    cudaGetSymbolAddress((void**)&ahi,  g_ahi);
    cudaGetSymbolAddress((void**)&alo,  g_alo);
    cudaGetSymbolAddress((void**)&w3hi, g_w3hi);
    cudaGetSymbolAddress((void**)&w3lo, g_w3lo);
    cudaGetSymbolAddress((void**)&whi,  g_whi);
    cudaGetSymbolAddress((void**)&wlo,  g_wlo);
    cudaGetSymbolAddress((void**)&qh,   g_qh);
    cudaGetSymbolAddress((void**)&ql,   g_ql);
    cudaGetSymbolAddress((void**)&kh,   g_kh);
    cudaGetSymbolAddress((void**)&kl,   g_kl);
    cudaGetSymbolAddress((void**)&vh,   g_vh);
    cudaGetSymbolAddress((void**)&vl,   g_vl);
    cudaGetSymbolAddress((void**)&tab,  g_tab);

    cudaFuncSetAttribute(mma_gemm_kernel<0>,
                         cudaFuncAttributeMaxDynamicSharedMemorySize, GEMM_SMEM);
    cudaFuncSetAttribute(mma_gemm_kernel<1>,
                         cudaFuncAttributeMaxDynamicSharedMemorySize, GEMM_SMEM);
    cudaFuncSetAttribute(flash_mma_kernel,
                         cudaFuncAttributeMaxDynamicSharedMemorySize, FLASH_SMEM);

    const int nx4 = (M_ROWS * D_DIM) / 4;
    const int nw4 = (D_DIM * D_DIM) / 4;
    const int WSZ = D_DIM * D_DIM;

    // RoPE table
    tab_kernel<<<(S_LEN * 64 + 255) / 256, 256>>>(tab);

    // splits: x, [Wq;Wk;Wv], Wo
    split_kernel<<<(nx4 + 255) / 256, 256>>>(x, ahi, alo, nx4);
    split_kernel<<<(nw4 + 255) / 256, 256>>>(Wq, w3hi,          w3lo,          nw4);
    split_kernel<<<(nw4 + 255) / 256, 256>>>(Wk, w3hi + WSZ,    w3lo + WSZ,    nw4);
    split_kernel<<<(nw4 + 255) / 256, 256>>>(Wv, w3hi + 2*WSZ,  w3lo + 2*WSZ,  nw4);
    split_kernel<<<(nw4 + 255) / 256, 256>>>(Wo, whi, wlo, nw4);

    // Fused QKV projection + rope/split epilogue
    dim3 qkv_grid(3 * D_DIM / BN, M_ROWS / BM);   // (48, 32)
    mma_gemm_kernel<1><<<qkv_grid, 256, GEMM_SMEM>>>(
        ahi, alo, w3hi, w3lo, nullptr,
        qh, ql, kh, kl, vh, vl, tab, M_ROWS, 3 * D_DIM, D_DIM);

    // Flash attention -> ctx bf16 hi/lo (reuses ahi/alo buffers)
    dim3 flash_grid(B_SZ * H_NUM, S_LEN / 128);   // (32, 16)
    flash_mma_kernel<<<flash_grid, 256, FLASH_SMEM>>>(qh, ql, kh, kl, vh, vl,
                                                      ahi, alo);

    // Output projection (fp32 epilogue to d_out)
    dim3 ggrid(D_DIM / BN, M_ROWS / BM);          // (16, 32)
    mma_gemm_kernel<0><<<ggrid, 256, GEMM_SMEM>>>(
        ahi, alo, whi, wlo, out,
        nullptr, nullptr, nullptr, nullptr, nullptr, nullptr, nullptr,
        M_ROWS, D_DIM, D_DIM);
}

// round 8
// speedup vs baseline: 3.0299x; 1.0921x over previous
#include <cuda_runtime.h>
#include <cuda_bf16.h>
#include <math.h>
#include <cstdint>

// Problem constants
#define B_SZ   2
#define S_LEN  2048
#define D_DIM  2048
#define H_NUM  16
#define HD     128
#define M_ROWS (B_SZ * S_LEN)   // 4096

// ---------------------------------------------------------------------------
// Scratch (static device globals)
// ---------------------------------------------------------------------------
__device__ __nv_bfloat16 g_ahi[M_ROWS * D_DIM];       // x hi, later ctx hi
__device__ __nv_bfloat16 g_alo[M_ROWS * D_DIM];       // x lo, later ctx lo
__device__ __nv_bfloat16 g_w3hi[3 * D_DIM * D_DIM];   // [Wq;Wk;Wv] hi
__device__ __nv_bfloat16 g_w3lo[3 * D_DIM * D_DIM];   // [Wq;Wk;Wv] lo
__device__ __nv_bfloat16 g_whi[D_DIM * D_DIM];        // Wo hi
__device__ __nv_bfloat16 g_wlo[D_DIM * D_DIM];        // Wo lo
__device__ __nv_bfloat16 g_qh [M_ROWS * D_DIM];
__device__ __nv_bfloat16 g_ql [M_ROWS * D_DIM];
__device__ __nv_bfloat16 g_kh [M_ROWS * D_DIM];
__device__ __nv_bfloat16 g_kl [M_ROWS * D_DIM];
__device__ __nv_bfloat16 g_vh [M_ROWS * D_DIM];
__device__ __nv_bfloat16 g_vl [M_ROWS * D_DIM];
__device__ float2 g_tab[S_LEN * 64];                  // rope (cos,sin) table

// ---------------------------------------------------------------------------
// PTX helpers
// ---------------------------------------------------------------------------
__device__ __forceinline__ uint32_t smem_u32(const void* p) {
    uint32_t a;
    asm("{ .reg .u64 t; cvta.to.shared.u64 t, %1; cvt.u32.u64 %0, t; }"
        : "=r"(a) : "l"(p));
    return a;
}
__device__ __forceinline__ void cp16(uint32_t s, const void* g) {
    asm volatile("cp.async.cg.shared.global [%0], [%1], 16;" :: "r"(s), "l"(g));
}
#define CP_COMMIT() asm volatile("cp.async.commit_group;" ::: "memory")
#define CP_WAIT(n)  asm volatile("cp.async.wait_group %0;" :: "n"(n) : "memory")

__device__ __forceinline__ void ldsm_x4(uint32_t* r, uint32_t addr) {
    asm volatile("ldmatrix.sync.aligned.m8n8.x4.shared.b16 {%0,%1,%2,%3}, [%4];"
                 : "=r"(r[0]), "=r"(r[1]), "=r"(r[2]), "=r"(r[3]) : "r"(addr));
}
__device__ __forceinline__ void ldsm_x4_t(uint32_t* r, uint32_t addr) {
    asm volatile("ldmatrix.sync.aligned.m8n8.x4.trans.shared.b16 {%0,%1,%2,%3}, [%4];"
                 : "=r"(r[0]), "=r"(r[1]), "=r"(r[2]), "=r"(r[3]) : "r"(addr));
}
__device__ __forceinline__ void mma16816(float* d, const uint32_t* a,
                                         const uint32_t* b) {
    asm volatile(
        "mma.sync.aligned.m16n8k16.row.col.f32.bf16.bf16.f32 "
        "{%0,%1,%2,%3}, {%4,%5,%6,%7}, {%8,%9}, {%0,%1,%2,%3};"
        : "+f"(d[0]), "+f"(d[1]), "+f"(d[2]), "+f"(d[3])
        : "r"(a[0]), "r"(a[1]), "r"(a[2]), "r"(a[3]), "r"(b[0]), "r"(b[1]));
}
__device__ __forceinline__ float ex2(float x) {
    float y;
    asm("ex2.approx.ftz.f32 %0, %1;" : "=f"(y) : "f"(x));
    return y;
}
__device__ __forceinline__ uint32_t pk_hi(float a, float b) {
    __nv_bfloat162 t = __floats2bfloat162_rn(a, b);
    return *(uint32_t*)&t;
}
__device__ __forceinline__ uint32_t pk_lo(float a, float b, uint32_t hi) {
    __nv_bfloat162 h = *(__nv_bfloat162*)&hi;
    return pk_hi(a - __bfloat162float(h.x), b - __bfloat162float(h.y));
}

// ---------------------------------------------------------------------------
// RoPE table
// ---------------------------------------------------------------------------
__global__ void tab_kernel(float2* __restrict__ T)
{
    int idx = blockIdx.x * blockDim.x + threadIdx.x;
    if (idx >= S_LEN * 64) return;
    int s = idx >> 6;
    int i = idx & 63;
    float inv = powf(10000.f, -(float)(2 * i) / 128.f);
    float ang = (float)s * inv;
    float sv, cv;
    sincosf(ang, &sv, &cv);
    T[idx] = make_float2(cv, sv);
}

// ---------------------------------------------------------------------------
// split: fp32 -> (hi bf16, lo bf16)
// ---------------------------------------------------------------------------
__global__ void split_kernel(const float* __restrict__ X,
                             __nv_bfloat16* __restrict__ H,
                             __nv_bfloat16* __restrict__ L, int n4)
{
    int i = blockIdx.x * blockDim.x + threadIdx.x;
    if (i >= n4) return;
    float4 v = ((const float4*)X)[i];
    uint32_t h0 = pk_hi(v.x, v.y), h1 = pk_hi(v.z, v.w);
    uint32_t l0 = pk_lo(v.x, v.y, h0), l1 = pk_lo(v.z, v.w, h1);
    ((uint2*)H)[i] = make_uint2(h0, h1);
    ((uint2*)L)[i] = make_uint2(l0, l1);
}

// ---------------------------------------------------------------------------
// HMMA bf16 split GEMM core: 128x128 CTA tile, 4 warps (2x2) of 64x64 tiles,
// 2 CTAs/SM. MODE 0: fp32 C out. MODE 1: fused QKV epilogue.
// ---------------------------------------------------------------------------
#define BM 128
#define BN 128
#define BK 32
#define PIT 40
#define TILE_B (BM * PIT * 2)        // 10240 bytes per array
#define STAGE_B (4 * TILE_B)         // 40960
#define GEMM_SMEM (2 * STAGE_B)      // 81920

__device__ __forceinline__ void g_load_stage(
    uint32_t st, const __nv_bfloat16* __restrict__ Ah,
    const __nv_bfloat16* __restrict__ Al, const __nv_bfloat16* __restrict__ Bh,
    const __nv_bfloat16* __restrict__ Bl, int bm, int bn, int k0, int K, int tid)
{
#pragma unroll
    for (int it = 0; it < 16; it++) {
        int c = tid + it * 128;
        int arr = c >> 9;
        int r   = (c & 511) >> 2;
        int c16 = c & 3;
        uint32_t dst = st + arr * TILE_B + r * (PIT * 2) + c16 * 16;
        const __nv_bfloat16* src;
        if (arr == 0)      src = Ah + (size_t)(bm + r) * K + k0 + c16 * 8;
        else if (arr == 1) src = Al + (size_t)(bm + r) * K + k0 + c16 * 8;
        else if (arr == 2) src = Bh + (size_t)(bn + r) * K + k0 + c16 * 8;
        else               src = Bl + (size_t)(bn + r) * K + k0 + c16 * 8;
        cp16(dst, src);
    }
}

template <int MODE>
__global__ void __launch_bounds__(128, 2)
mma_gemm_kernel(const __nv_bfloat16* __restrict__ Ah,
                const __nv_bfloat16* __restrict__ Al,
                const __nv_bfloat16* __restrict__ Bh,
                const __nv_bfloat16* __restrict__ Bl,
                float* __restrict__ C,
                __nv_bfloat16* __restrict__ QH, __nv_bfloat16* __restrict__ QL,
                __nv_bfloat16* __restrict__ KH, __nv_bfloat16* __restrict__ KL,
                __nv_bfloat16* __restrict__ VH, __nv_bfloat16* __restrict__ VL,
                const float2* __restrict__ tab,
                int M, int N, int K)
{
    extern __shared__ char smem[];
    const uint32_t sb = smem_u32(smem);

    const int tid  = threadIdx.x;
    const int wid  = tid >> 5;
    const int lane = tid & 31;
    const int wy   = wid >> 1;           // 0..1 (64-row band)
    const int wx   = wid & 1;            // 0..1 (64-col band)
    const int bm = blockIdx.y * BM;
    const int bn = blockIdx.x * BN;

    float acc[4][8][4];
#pragma unroll
    for (int mt = 0; mt < 4; mt++)
#pragma unroll
        for (int nt = 0; nt < 8; nt++)
#pragma unroll
            for (int e = 0; e < 4; e++) acc[mt][nt][e] = 0.f;

    // ldmatrix per-lane base offsets
    const int a_row = wy * 64 + (lane & 15);
    const int a_kof = (lane >> 4) * 8;
    const int b_row = wx * 64 + (lane & 7) + ((lane >> 4) << 3);
    const int b_kof = ((lane >> 3) & 1) * 8;

    const int nk = K / BK;

    g_load_stage(sb, Ah, Al, Bh, Bl, bm, bn, 0, K, tid);
    CP_COMMIT();

    for (int i = 0; i < nk; i++) {
        const uint32_t st = sb + (i & 1) * STAGE_B;
        if (i + 1 < nk) {
            g_load_stage(sb + ((i + 1) & 1) * STAGE_B,
                         Ah, Al, Bh, Bl, bm, bn, (i + 1) * BK, K, tid);
            CP_COMMIT();
            CP_WAIT(1);
        } else {
            CP_WAIT(0);
        }
        __syncthreads();

        const uint32_t sAh = st;
        const uint32_t sAl = st + TILE_B;
        const uint32_t sBh = st + 2 * TILE_B;
        const uint32_t sBl = st + 3 * TILE_B;

#pragma unroll
        for (int ks = 0; ks < 2; ks++) {
            const int kk = ks * 16;
            uint32_t fah[4][4], fal[4][4], fbh[4][4], fbl[4][4];
#pragma unroll
            for (int mt = 0; mt < 4; mt++) {
                uint32_t off = (uint32_t)(a_row + mt * 16) * (PIT * 2)
                               + (uint32_t)(kk + a_kof) * 2;
                ldsm_x4(fah[mt], sAh + off);
                ldsm_x4(fal[mt], sAl + off);
            }
#pragma unroll
            for (int np = 0; np < 4; np++) {
                uint32_t off = (uint32_t)(b_row + np * 16) * (PIT * 2)
                               + (uint32_t)(kk + b_kof) * 2;
                ldsm_x4(fbh[np], sBh + off);
                ldsm_x4(fbl[np], sBl + off);
            }
#pragma unroll
            for (int mt = 0; mt < 4; mt++)
#pragma unroll
                for (int np = 0; np < 4; np++) {
                    mma16816(acc[mt][2 * np],     fah[mt], fbh[np]);
                    mma16816(acc[mt][2 * np + 1], fah[mt], fbh[np] + 2);
                    mma16816(acc[mt][2 * np],     fah[mt], fbl[np]);
                    mma16816(acc[mt][2 * np + 1], fah[mt], fbl[np] + 2);
                    mma16816(acc[mt][2 * np],     fal[mt], fbh[np]);
                    mma16816(acc[mt][2 * np + 1], fal[mt], fbh[np] + 2);
                }
        }
        __syncthreads();
    }

    const int er = lane >> 2;
    const int ec = (lane & 3) * 2;

    if (MODE == 0) {
#pragma unroll
        for (int mt = 0; mt < 4; mt++) {
            const int r0 = bm + wy * 64 + mt * 16 + er;
#pragma unroll
            for (int nt = 0; nt < 8; nt++) {
                const int c0 = bn + wx * 64 + nt * 8 + ec;
                *(float2*)&C[(size_t)r0 * N + c0] =
                    make_float2(acc[mt][nt][0], acc[mt][nt][1]);
                *(float2*)&C[(size_t)(r0 + 8) * N + c0] =
                    make_float2(acc[mt][nt][2], acc[mt][nt][3]);
            }
        }
    } else {
        const int sel = bn >> 11;                 // 0=q, 1=k, 2=v
        __nv_bfloat16* H = (sel == 0) ? QH : (sel == 1) ? KH : VH;
        __nv_bfloat16* L = (sel == 0) ? QL : (sel == 1) ? KL : VL;
#pragma unroll
        for (int mt = 0; mt < 4; mt++) {
            const int r0 = bm + wy * 64 + mt * 16 + er;
            const int r1 = r0 + 8;
#pragma unroll
            for (int nt = 0; nt < 8; nt++) {
                const int c = (bn + wx * 64 + nt * 8 + ec) & 2047;
                float a0 = acc[mt][nt][0], a1 = acc[mt][nt][1];
                float b0 = acc[mt][nt][2], b1 = acc[mt][nt][3];
                if (sel < 2) {
                    const int pair = (c & 127) >> 1;
                    float2 t0 = tab[(r0 & (S_LEN - 1)) * 64 + pair];
                    float2 t1 = tab[(r1 & (S_LEN - 1)) * 64 + pair];
                    float rx0 = a0 * t0.x - a1 * t0.y;
                    float ry0 = a0 * t0.y + a1 * t0.x;
                    float rx1 = b0 * t1.x - b1 * t1.y;
                    float ry1 = b0 * t1.y + b1 * t1.x;
                    a0 = rx0; a1 = ry0; b0 = rx1; b1 = ry1;
                }
                uint32_t h0 = pk_hi(a0, a1), l0 = pk_lo(a0, a1, h0);
                uint32_t h1 = pk_hi(b0, b1), l1 = pk_lo(b0, b1, h1);
                const size_t p0 = ((size_t)r0 * D_DIM + c) >> 1;
                const size_t p1 = ((size_t)r1 * D_DIM + c) >> 1;
                ((uint32_t*)H)[p0] = h0;
                ((uint32_t*)L)[p0] = l0;
                ((uint32_t*)H)[p1] = h1;
                ((uint32_t*)L)[p1] = l1;
            }
        }
    }
}

// ---------------------------------------------------------------------------
// Flash attention, HMMA bf16 hi/lo (unchanged)
// ---------------------------------------------------------------------------
#define FPITCH 272
#define FQ_B   (128 * FPITCH)
#define FKV_A  (64 * FPITCH)
#define SQH_O  0
#define SQL_O  FQ_B
#define SKV_O  (2 * FQ_B)
#define KV_STAGE_B (4 * FKV_A)
#define FLASH_SMEM (2 * FQ_B + 2 * KV_STAGE_B)

__device__ __forceinline__ void f_load_kv(
    uint32_t st, const __nv_bfloat16* __restrict__ Kh,
    const __nv_bfloat16* __restrict__ Kl, const __nv_bfloat16* __restrict__ Vh,
    const __nv_bfloat16* __restrict__ Vl, size_t base, int kb, int tid)
{
#pragma unroll
    for (int it = 0; it < 16; it++) {
        int c = tid + it * 256;
        int arr = c >> 10;
        int r   = (c >> 4) & 63;
        int ch  = c & 15;
        uint32_t dst = st + arr * FKV_A + r * FPITCH + ch * 16;
        const __nv_bfloat16* src;
        size_t ge = base + (size_t)(kb + r) * D_DIM + ch * 8;
        if (arr == 0)      src = Kh + ge;
        else if (arr == 1) src = Kl + ge;
        else if (arr == 2) src = Vh + ge;
        else               src = Vl + ge;
        cp16(dst, src);
    }
}

__global__ void __launch_bounds__(256, 1)
flash_mma_kernel(const __nv_bfloat16* __restrict__ Qh,
                 const __nv_bfloat16* __restrict__ Ql,
                 const __nv_bfloat16* __restrict__ Kh,
                 const __nv_bfloat16* __restrict__ Kl,
                 const __nv_bfloat16* __restrict__ Vh,
                 const __nv_bfloat16* __restrict__ Vl,
                 __nv_bfloat16* __restrict__ OH,
                 __nv_bfloat16* __restrict__ OL)
{
    extern __shared__ char smc[];
    const uint32_t sb = smem_u32(smc);

    const int tid  = threadIdx.x;
    const int wid  = tid >> 5;
    const int lane = tid & 31;
    const int bh = blockIdx.x;
    const int b  = bh >> 4;
    const int h  = bh & 15;
    const int qt = (int)gridDim.y - 1 - (int)blockIdx.y;
    const int q0 = qt * 128;
    const size_t base = (size_t)b * S_LEN * D_DIM + (size_t)h * HD;
    const int nkt = 2 * (qt + 1);

#pragma unroll
    for (int it = 0; it < 16; it++) {
        int c = tid + it * 256;
        int arr = c >> 11;
        int r   = (c >> 4) & 127;
        int ch  = c & 15;
        uint32_t dst = sb + (arr ? SQL_O : SQH_O) + r * FPITCH + ch * 16;
        const __nv_bfloat16* src = (arr ? Ql : Qh)
                                   + base + (size_t)(q0 + r) * D_DIM + ch * 8;
        cp16(dst, src);
    }
    f_load_kv(sb + SKV_O, Kh, Kl, Vh, Vl, base, 0, tid);
    CP_COMMIT();

    const int wrow = wid * 16;
    float o[16][4];
#pragma unroll
    for (int nt = 0; nt < 16; nt++)
#pragma unroll
        for (int e = 0; e < 4; e++) o[nt][e] = 0.f;
    float m0 = -1e30f, m1 = -1e30f, l0 = 0.f, l1 = 0.f;
    const float sc = 0.08838834764831845f * 1.4426950408889634f;
    const unsigned FULL = 0xffffffffu;

    for (int t = 0; t < nkt; t++) {
        const uint32_t st = sb + SKV_O + (t & 1) * KV_STAGE_B;
        if (t + 1 < nkt) {
            f_load_kv(sb + SKV_O + ((t + 1) & 1) * KV_STAGE_B,
                      Kh, Kl, Vh, Vl, base, (t + 1) * 64, tid);
            CP_COMMIT();
            CP_WAIT(1);
        } else {
            CP_WAIT(0);
        }
        __syncthreads();

        const uint32_t KHs = st;
        const uint32_t KLs = st + FKV_A;
        const uint32_t VHs = st + 2 * FKV_A;
        const uint32_t VLs = st + 3 * FKV_A;
        const int kb = t * 64;

        float s[8][4];
#pragma unroll
        for (int nt = 0; nt < 8; nt++)
#pragma unroll
            for (int e = 0; e < 4; e++) s[nt][e] = 0.f;

#pragma unroll
        for (int kk = 0; kk < 8; kk++) {
            uint32_t aoff = (uint32_t)(wrow + (lane & 15)) * FPITCH
                            + (uint32_t)(kk * 16 + (lane >> 4) * 8) * 2;
            uint32_t ah[4], al[4];
            ldsm_x4(ah, sb + SQH_O + aoff);
            ldsm_x4(al, sb + SQL_O + aoff);
#pragma unroll
            for (int np = 0; np < 4; np++) {
                uint32_t boff = (uint32_t)(np * 16 + (lane & 7) + ((lane >> 4) << 3)) * FPITCH
                                + (uint32_t)(kk * 16 + (((lane >> 3) & 1) << 3)) * 2;
                uint32_t bh4[4], bl4[4];
                ldsm_x4(bh4, KHs + boff);
                ldsm_x4(bl4, KLs + boff);
                mma16816(s[2 * np],     ah, bh4);
                mma16816(s[2 * np + 1], ah, bh4 + 2);
                mma16816(s[2 * np],     ah, bl4);
                mma16816(s[2 * np + 1], ah, bl4 + 2);
                mma16816(s[2 * np],     al, bh4);
                mma16816(s[2 * np + 1], al, bh4 + 2);
            }
        }

        if (t + 2 >= nkt) {
            const int row0 = q0 + wrow + (lane >> 2);
            const int row1 = row0 + 8;
            const int cbse = kb + ((lane & 3) << 1);
#pragma unroll
            for (int nt = 0; nt < 8; nt++) {
                const int c = cbse + nt * 8;
                if (c     > row0) s[nt][0] = -1e30f;
                if (c + 1 > row0) s[nt][1] = -1e30f;
                if (c     > row1) s[nt][2] = -1e30f;
                if (c + 1 > row1) s[nt][3] = -1e30f;
            }
        }
        float mx0 = -1e30f, mx1 = -1e30f;
#pragma unroll
        for (int nt = 0; nt < 8; nt++) {
            mx0 = fmaxf(mx0, fmaxf(s[nt][0], s[nt][1]));
            mx1 = fmaxf(mx1, fmaxf(s[nt][2], s[nt][3]));
        }
        mx0 = fmaxf(mx0, __shfl_xor_sync(FULL, mx0, 1));
        mx0 = fmaxf(mx0, __shfl_xor_sync(FULL, mx0, 2));
        mx1 = fmaxf(mx1, __shfl_xor_sync(FULL, mx1, 1));
        mx1 = fmaxf(mx1, __shfl_xor_sync(FULL, mx1, 2));
        const float mn0 = fmaxf(m0, mx0);
        const float mn1 = fmaxf(m1, mx1);
        const float cr0 = ex2((m0 - mn0) * sc);
        const float cr1 = ex2((m1 - mn1) * sc);
        m0 = mn0; m1 = mn1;
        float rs0 = 0.f, rs1 = 0.f;
#pragma unroll
        for (int nt = 0; nt < 8; nt++) {
            s[nt][0] = ex2((s[nt][0] - mn0) * sc);
            s[nt][1] = ex2((s[nt][1] - mn0) * sc);
            s[nt][2] = ex2((s[nt][2] - mn1) * sc);
            s[nt][3] = ex2((s[nt][3] - mn1) * sc);
            rs0 += s[nt][0] + s[nt][1];
            rs1 += s[nt][2] + s[nt][3];
        }
        rs0 += __shfl_xor_sync(FULL, rs0, 1);
        rs0 += __shfl_xor_sync(FULL, rs0, 2);
        rs1 += __shfl_xor_sync(FULL, rs1, 1);
        rs1 += __shfl_xor_sync(FULL, rs1, 2);
        l0 = l0 * cr0 + rs0;
        l1 = l1 * cr1 + rs1;
#pragma unroll
        for (int nt = 0; nt < 16; nt++) {
            o[nt][0] *= cr0; o[nt][1] *= cr0;
            o[nt][2] *= cr1; o[nt][3] *= cr1;
        }

        uint32_t ph[4][4], pl[4][4];
#pragma unroll
        for (int j = 0; j < 4; j++) {
            ph[j][0] = pk_hi(s[2 * j][0],     s[2 * j][1]);
            ph[j][1] = pk_hi(s[2 * j][2],     s[2 * j][3]);
            ph[j][2] = pk_hi(s[2 * j + 1][0], s[2 * j + 1][1]);
            ph[j][3] = pk_hi(s[2 * j + 1][2], s[2 * j + 1][3]);
            pl[j][0] = pk_lo(s[2 * j][0],     s[2 * j][1],     ph[j][0]);
            pl[j][1] = pk_lo(s[2 * j][2],     s[2 * j][3],     ph[j][1]);
            pl[j][2] = pk_lo(s[2 * j + 1][0], s[2 * j + 1][1], ph[j][2]);
            pl[j][3] = pk_lo(s[2 * j + 1][2], s[2 * j + 1][3], ph[j][3]);
        }

#pragma unroll
        for (int j = 0; j < 4; j++) {
#pragma unroll
            for (int nd = 0; nd < 8; nd++) {
                uint32_t boff = (uint32_t)(j * 16 + (lane & 7) + (((lane >> 3) & 1) << 3)) * FPITCH
                                + (uint32_t)(nd * 16 + ((lane >> 4) << 3)) * 2;
                uint32_t vh4[4], vl4[4];
                ldsm_x4_t(vh4, VHs + boff);
                ldsm_x4_t(vl4, VLs + boff);
                mma16816(o[2 * nd],     ph[j], vh4);
                mma16816(o[2 * nd + 1], ph[j], vh4 + 2);
                mma16816(o[2 * nd],     ph[j], vl4);
                mma16816(o[2 * nd + 1], ph[j], vl4 + 2);
                mma16816(o[2 * nd],     pl[j], vh4);
                mma16816(o[2 * nd + 1], pl[j], vh4 + 2);
            }
        }
        __syncthreads();
    }

    const float i0 = 1.f / l0;
    const float i1 = 1.f / l1;
    const int r0 = q0 + wrow + (lane >> 2);
    const int r1 = r0 + 8;
#pragma unroll
    for (int nt = 0; nt < 16; nt++) {
        const int col = nt * 8 + ((lane & 3) << 1);
        float a0 = o[nt][0] * i0, a1 = o[nt][1] * i0;
        float b0 = o[nt][2] * i1, b1 = o[nt][3] * i1;
        uint32_t h0 = pk_hi(a0, a1), L0 = pk_lo(a0, a1, h0);
        uint32_t h1 = pk_hi(b0, b1), L1 = pk_lo(b0, b1, h1);
        const size_t p0 = (base + (size_t)r0 * D_DIM + col) >> 1;
        const size_t p1 = (base + (size_t)r1 * D_DIM + col) >> 1;
        ((uint32_t*)OH)[p0] = h0;
        ((uint32_t*)OL)[p0] = L0;
        ((uint32_t*)OH)[p1] = h1;
        ((uint32_t*)OL)[p1] = L1;
    }
}

// ---------------------------------------------------------------------------
// Launcher
// ---------------------------------------------------------------------------
extern "C" void kernel_launch(void* const* d_in, const int* in_sizes, int n_in,
                              void* d_out, int out_size)
{
    const float* x  = (const float*)d_in[0];
    const float* Wq = (const float*)d_in[1];
    const float* Wk = (const float*)d_in[2];
    const float* Wv = (const float*)d_in[3];
    const float* Wo = (const float*)d_in[4];
    float* out = (float*)d_out;

    __nv_bfloat16 *ahi, *alo, *w3hi, *w3lo, *whi, *wlo, *qh, *ql, *kh, *kl, *vh, *vl;
    float2* tab;
    cudaGetSymbolAddress((void**)&ahi,  g_ahi);
    cudaGetSymbolAddress((void**)&alo,  g_alo);
    cudaGetSymbolAddress((void**)&w3hi, g_w3hi);
    cudaGetSymbolAddress((void**)&w3lo, g_w3lo);
    cudaGetSymbolAddress((void**)&whi,  g_whi);
    cudaGetSymbolAddress((void**)&wlo,  g_wlo);
    cudaGetSymbolAddress((void**)&qh,   g_qh);
    cudaGetSymbolAddress((void**)&ql,   g_ql);
    cudaGetSymbolAddress((void**)&kh,   g_kh);
    cudaGetSymbolAddress((void**)&kl,   g_kl);
    cudaGetSymbolAddress((void**)&vh,   g_vh);
    cudaGetSymbolAddress((void**)&vl,   g_vl);
    cudaGetSymbolAddress((void**)&tab,  g_tab);

    cudaFuncSetAttribute(mma_gemm_kernel<0>,
                         cudaFuncAttributeMaxDynamicSharedMemorySize, GEMM_SMEM);
    cudaFuncSetAttribute(mma_gemm_kernel<1>,
                         cudaFuncAttributeMaxDynamicSharedMemorySize, GEMM_SMEM);
    cudaFuncSetAttribute(flash_mma_kernel,
                         cudaFuncAttributeMaxDynamicSharedMemorySize, FLASH_SMEM);

    const int nx4 = (M_ROWS * D_DIM) / 4;
    const int nw4 = (D_DIM * D_DIM) / 4;
    const int WSZ = D_DIM * D_DIM;

    // RoPE table
    tab_kernel<<<(S_LEN * 64 + 255) / 256, 256>>>(tab);

    // splits: x, [Wq;Wk;Wv], Wo
    split_kernel<<<(nx4 + 255) / 256, 256>>>(x, ahi, alo, nx4);
    split_kernel<<<(nw4 + 255) / 256, 256>>>(Wq, w3hi,          w3lo,          nw4);
    split_kernel<<<(nw4 + 255) / 256, 256>>>(Wk, w3hi + WSZ,    w3lo + WSZ,    nw4);
    split_kernel<<<(nw4 + 255) / 256, 256>>>(Wv, w3hi + 2*WSZ,  w3lo + 2*WSZ,  nw4);
    split_kernel<<<(nw4 + 255) / 256, 256>>>(Wo, whi, wlo, nw4);

    // Fused QKV projection + rope/split epilogue
    dim3 qkv_grid(3 * D_DIM / BN, M_ROWS / BM);   // (48, 32)
    mma_gemm_kernel<1><<<qkv_grid, 128, GEMM_SMEM>>>(
        ahi, alo, w3hi, w3lo, nullptr,
        qh, ql, kh, kl, vh, vl, tab, M_ROWS, 3 * D_DIM, D_DIM);

    // Flash attention -> ctx bf16 hi/lo (reuses ahi/alo buffers)
    dim3 flash_grid(B_SZ * H_NUM, S_LEN / 128);   // (32, 16)
    flash_mma_kernel<<<flash_grid, 256, FLASH_SMEM>>>(qh, ql, kh, kl, vh, vl,
                                                      ahi, alo);

    // Output projection (fp32 epilogue to d_out)
    dim3 ggrid(D_DIM / BN, M_ROWS / BM);          // (16, 32)
    mma_gemm_kernel<0><<<ggrid, 128, GEMM_SMEM>>>(
        ahi, alo, whi, wlo, out,
        nullptr, nullptr, nullptr, nullptr, nullptr, nullptr, nullptr,
        M_ROWS, D_DIM, D_DIM);
}